// round 1
// baseline (speedup 1.0000x reference)
#include <cuda_runtime.h>
#include <math.h>

#define B 2
#define S 2048
#define HQ 32
#define HK 8
#define D 128
#define G 4
#define WINDOW 1024

#define BQ 32            // queries per block
#define BK 64            // keys per tile
#define ROWS 128         // BQ * G query-head rows per block
#define QS_STRIDE 132
#define KS_STRIDE 132
#define VS_STRIDE 132
#define SS_STRIDE 65

// Scratch for RoPE'd Q and K (device globals: allocation-free rule)
__device__ float g_qr[(size_t)B * S * HQ * D];
__device__ float g_kr[(size_t)B * S * HK * D];

// ---------------------------------------------------------------------------
// Kernel 1: apply RoPE to Q and K, store to scratch. One block per token.
// ---------------------------------------------------------------------------
__global__ void rope_kernel(const float* __restrict__ q,
                            const float* __restrict__ k,
                            const int* __restrict__ pos) {
    const int token = blockIdx.x;      // 0 .. B*S-1
    const int tid = threadIdx.x;       // 256 threads

    __shared__ float cs[64], sn[64];
    if (tid < 64) {
        float inv = powf(10000.0f, -((float)tid) / 64.0f);
        float ang = (float)pos[token] * inv;
        float s, c;
        sincosf(ang, &s, &c);
        cs[tid] = c;
        sn[tid] = s;
    }
    __syncthreads();

    const float* qrow = q + (size_t)token * (HQ * D);
    float* qo = g_qr + (size_t)token * (HQ * D);
    for (int idx = tid; idx < HQ * 64; idx += blockDim.x) {
        int h = idx >> 6, d = idx & 63;
        float x1 = qrow[h * D + d];
        float x2 = qrow[h * D + 64 + d];
        float c = cs[d], s = sn[d];
        qo[h * D + d]      = x1 * c - x2 * s;
        qo[h * D + 64 + d] = x2 * c + x1 * s;
    }

    const float* krow = k + (size_t)token * (HK * D);
    float* ko = g_kr + (size_t)token * (HK * D);
    for (int idx = tid; idx < HK * 64; idx += blockDim.x) {
        int h = idx >> 6, d = idx & 63;
        float x1 = krow[h * D + d];
        float x2 = krow[h * D + 64 + d];
        float c = cs[d], s = sn[d];
        ko[h * D + d]      = x1 * c - x2 * s;
        ko[h * D + 64 + d] = x2 * c + x1 * s;
    }
}

// ---------------------------------------------------------------------------
// Kernel 2: flash attention. Block = (q_tile, hk, b). 128 rows share K/V.
// ---------------------------------------------------------------------------
__global__ void __launch_bounds__(256, 1)
attn_kernel(const float* __restrict__ value, float* __restrict__ out) {
    const int qt = blockIdx.x;
    const int hk = blockIdx.y;
    const int b  = blockIdx.z;
    const int q0 = qt * BQ;
    const int tid = threadIdx.x;

    extern __shared__ float sm[];
    float* Qs   = sm;                                  // ROWS x QS_STRIDE
    float* Ks   = Qs + ROWS * QS_STRIDE;               // BK x KS_STRIDE
    float* Vs   = Ks + BK * KS_STRIDE;                 // BK x VS_STRIDE
    float* Ss   = Vs + BK * VS_STRIDE;                 // ROWS x SS_STRIDE
    float* rowm = Ss + ROWS * SS_STRIDE;
    float* rowl = rowm + ROWS;
    float* rsc  = rowl + ROWS;

    // --- load Q tile (rope'd) into smem ---
    for (int idx = tid * 4; idx < ROWS * D; idx += 256 * 4) {
        int r = idx >> 7, col = idx & 127;
        int i  = q0 + (r & (BQ - 1));
        int hq = hk * G + (r >> 5);
        const float4 v4 = *(const float4*)(g_qr +
            (((size_t)(b * S + i)) * HQ + hq) * D + col);
        *(float4*)(Qs + r * QS_STRIDE + col) = v4;
    }
    if (tid < ROWS) { rowm[tid] = -1e20f; rowl[tid] = 0.0f; }

    // PV accumulators: 8 rows x 8 dims (two float4 groups) per thread
    float4 olo[8], ohi[8];
#pragma unroll
    for (int i = 0; i < 8; i++) {
        olo[i] = make_float4(0.f, 0.f, 0.f, 0.f);
        ohi[i] = make_float4(0.f, 0.f, 0.f, 0.f);
    }

    const int sy = tid >> 3, sx = tid & 7;    // QK mapping: 32x8 thread grid
    const int ty = tid >> 4, tx = tid & 15;   // PV mapping: 16x16 thread grid

    int jmin = q0 - (WINDOW - 1);
    if (jmin < 0) jmin = 0;
    const int k0s = (jmin / BK) * BK;
    const int qhi = q0 + BQ - 1;
    const float scl = 0.08838834764831845f;   // 1/sqrt(128)

    for (int k0 = k0s; k0 <= qhi; k0 += BK) {
        __syncthreads();   // previous PV done with Vs/Ss

        // --- load K (rope'd) and V tiles ---
        for (int idx = tid * 4; idx < BK * D; idx += 256 * 4) {
            int r = idx >> 7, col = idx & 127;
            size_t gb = (((size_t)(b * S + k0 + r)) * HK + hk) * D + col;
            *(float4*)(Ks + r * KS_STRIDE + col) = *(const float4*)(g_kr + gb);
            *(float4*)(Vs + r * VS_STRIDE + col) = *(const float4*)(value + gb);
        }
        __syncthreads();

        // --- QK^T: each thread computes 4 rows x 8 keys ---
        float acc[4][8];
#pragma unroll
        for (int rr = 0; rr < 4; rr++)
#pragma unroll
            for (int cc = 0; cc < 8; cc++) acc[rr][cc] = 0.0f;

#pragma unroll 2
        for (int kk = 0; kk < D; kk += 4) {
            float4 qf[4], kf[8];
#pragma unroll
            for (int rr = 0; rr < 4; rr++)
                qf[rr] = *(const float4*)(Qs + (sy * 4 + rr) * QS_STRIDE + kk);
#pragma unroll
            for (int cc = 0; cc < 8; cc++)
                kf[cc] = *(const float4*)(Ks + (sx + cc * 8) * KS_STRIDE + kk);
#pragma unroll
            for (int rr = 0; rr < 4; rr++)
#pragma unroll
                for (int cc = 0; cc < 8; cc++) {
                    acc[rr][cc] += qf[rr].x * kf[cc].x;
                    acc[rr][cc] += qf[rr].y * kf[cc].y;
                    acc[rr][cc] += qf[rr].z * kf[cc].z;
                    acc[rr][cc] += qf[rr].w * kf[cc].w;
                }
        }

        // scale + sliding-window causal mask, store scores
#pragma unroll
        for (int rr = 0; rr < 4; rr++) {
            int r = sy * 4 + rr;
            int i = q0 + (r & (BQ - 1));
#pragma unroll
            for (int cc = 0; cc < 8; cc++) {
                int j = k0 + sx + cc * 8;
                float v = acc[rr][cc] * scl;
                if (j > i || (i - j) >= WINDOW) v = -1e30f;
                Ss[r * SS_STRIDE + sx + cc * 8] = v;
            }
        }
        __syncthreads();

        // --- online softmax: one thread per row ---
        if (tid < ROWS) {
            float m_old = rowm[tid];
            float* srow = Ss + tid * SS_STRIDE;
            float tm = -1e30f;
#pragma unroll 8
            for (int c = 0; c < BK; c++) tm = fmaxf(tm, srow[c]);
            float nm = fmaxf(m_old, tm);
            float sum = 0.0f;
#pragma unroll 8
            for (int c = 0; c < BK; c++) {
                float p = __expf(srow[c] - nm);
                srow[c] = p;
                sum += p;
            }
            float sc = __expf(m_old - nm);
            rowl[tid] = rowl[tid] * sc + sum;
            rowm[tid] = nm;
            rsc[tid]  = sc;
        }
        __syncthreads();

        // --- rescale O, then P@V ---
#pragma unroll
        for (int rr = 0; rr < 8; rr++) {
            float s = rsc[ty * 8 + rr];
            olo[rr].x *= s; olo[rr].y *= s; olo[rr].z *= s; olo[rr].w *= s;
            ohi[rr].x *= s; ohi[rr].y *= s; ohi[rr].z *= s; ohi[rr].w *= s;
        }
#pragma unroll 2
        for (int kk = 0; kk < BK; kk++) {
            float4 vlo = *(const float4*)(Vs + kk * VS_STRIDE + tx * 4);
            float4 vhi = *(const float4*)(Vs + kk * VS_STRIDE + 64 + tx * 4);
#pragma unroll
            for (int rr = 0; rr < 8; rr++) {
                float p = Ss[(ty * 8 + rr) * SS_STRIDE + kk];
                olo[rr].x += p * vlo.x; olo[rr].y += p * vlo.y;
                olo[rr].z += p * vlo.z; olo[rr].w += p * vlo.w;
                ohi[rr].x += p * vhi.x; ohi[rr].y += p * vhi.y;
                ohi[rr].z += p * vhi.z; ohi[rr].w += p * vhi.w;
            }
        }
    }

    // --- epilogue: normalize and write out ---
#pragma unroll
    for (int rr = 0; rr < 8; rr++) {
        int r = ty * 8 + rr;
        float inv = 1.0f / rowl[r];
        int i  = q0 + (r & (BQ - 1));
        int hq = hk * G + (r >> 5);
        float* ob = out + (((size_t)(b * S + i)) * HQ + hq) * D;
        float4 a = olo[rr], c = ohi[rr];
        a.x *= inv; a.y *= inv; a.z *= inv; a.w *= inv;
        c.x *= inv; c.y *= inv; c.z *= inv; c.w *= inv;
        *(float4*)(ob + tx * 4)      = a;
        *(float4*)(ob + 64 + tx * 4) = c;
    }
}

// ---------------------------------------------------------------------------
extern "C" void kernel_launch(void* const* d_in, const int* in_sizes, int n_in,
                              void* d_out, int out_size) {
    const float* q   = (const float*)d_in[0];
    const float* k   = (const float*)d_in[1];
    const float* v   = (const float*)d_in[2];
    const int*   pos = (const int*)d_in[3];
    float* out = (float*)d_out;

    const int smem_bytes =
        (ROWS * QS_STRIDE + BK * KS_STRIDE + BK * VS_STRIDE +
         ROWS * SS_STRIDE + 3 * ROWS) * (int)sizeof(float);
    cudaFuncSetAttribute(attn_kernel,
                         cudaFuncAttributeMaxDynamicSharedMemorySize,
                         smem_bytes);

    rope_kernel<<<B * S, 256>>>(q, k, pos);

    dim3 grid(S / BQ, HK, B);
    attn_kernel<<<grid, 256, smem_bytes>>>(v, out);
}

// round 2
// speedup vs baseline: 1.0008x; 1.0008x over previous
#include <cuda_runtime.h>
#include <math.h>

#define B 2
#define S 2048
#define HQ 32
#define HK 8
#define D 128
#define G 4
#define WINDOW 1024

#define BQ 32            // queries per block
#define BK 64            // keys per tile
#define ROWS 128         // BQ * G query-head rows per block
#define QS_STRIDE 132
#define KS_STRIDE 132
#define VS_STRIDE 132
#define SS_STRIDE 65

// Scratch for RoPE'd Q and K (device globals: allocation-free rule)
__device__ float g_qr[(size_t)B * S * HQ * D];
__device__ float g_kr[(size_t)B * S * HK * D];

// ---------------------------------------------------------------------------
// Kernel 1: apply RoPE to Q and K, store to scratch. One block per token.
// ---------------------------------------------------------------------------
__global__ void rope_kernel(const float* __restrict__ q,
                            const float* __restrict__ k,
                            const int* __restrict__ pos) {
    const int token = blockIdx.x;      // 0 .. B*S-1
    const int tid = threadIdx.x;       // 256 threads

    __shared__ float cs[64], sn[64];
    if (tid < 64) {
        float inv = powf(10000.0f, -((float)tid) / 64.0f);
        float ang = (float)pos[token] * inv;
        float s, c;
        sincosf(ang, &s, &c);
        cs[tid] = c;
        sn[tid] = s;
    }
    __syncthreads();

    const float* qrow = q + (size_t)token * (HQ * D);
    float* qo = g_qr + (size_t)token * (HQ * D);
    for (int idx = tid; idx < HQ * 64; idx += blockDim.x) {
        int h = idx >> 6, d = idx & 63;
        float x1 = qrow[h * D + d];
        float x2 = qrow[h * D + 64 + d];
        float c = cs[d], s = sn[d];
        qo[h * D + d]      = x1 * c - x2 * s;
        qo[h * D + 64 + d] = x2 * c + x1 * s;
    }

    const float* krow = k + (size_t)token * (HK * D);
    float* ko = g_kr + (size_t)token * (HK * D);
    for (int idx = tid; idx < HK * 64; idx += blockDim.x) {
        int h = idx >> 6, d = idx & 63;
        float x1 = krow[h * D + d];
        float x2 = krow[h * D + 64 + d];
        float c = cs[d], s = sn[d];
        ko[h * D + d]      = x1 * c - x2 * s;
        ko[h * D + 64 + d] = x2 * c + x1 * s;
    }
}

// ---------------------------------------------------------------------------
// Kernel 2: flash attention. Block = (q_tile, hk, b). 128 rows share K/V.
// ---------------------------------------------------------------------------
__global__ void __launch_bounds__(256, 1)
attn_kernel(const float* __restrict__ value, float* __restrict__ out) {
    const int qt = blockIdx.x;
    const int hk = blockIdx.y;
    const int b  = blockIdx.z;
    const int q0 = qt * BQ;
    const int tid = threadIdx.x;

    extern __shared__ float sm[];
    float* Qs   = sm;                                  // ROWS x QS_STRIDE
    float* Ks   = Qs + ROWS * QS_STRIDE;               // BK x KS_STRIDE
    float* Vs   = Ks + BK * KS_STRIDE;                 // BK x VS_STRIDE
    float* Ss   = Vs + BK * VS_STRIDE;                 // ROWS x SS_STRIDE
    float* rowm = Ss + ROWS * SS_STRIDE;
    float* rowl = rowm + ROWS;
    float* rsc  = rowl + ROWS;

    // --- load Q tile (rope'd) into smem ---
    for (int idx = tid * 4; idx < ROWS * D; idx += 256 * 4) {
        int r = idx >> 7, col = idx & 127;
        int i  = q0 + (r & (BQ - 1));
        int hq = hk * G + (r >> 5);
        const float4 v4 = *(const float4*)(g_qr +
            (((size_t)(b * S + i)) * HQ + hq) * D + col);
        *(float4*)(Qs + r * QS_STRIDE + col) = v4;
    }
    if (tid < ROWS) { rowm[tid] = -1e20f; rowl[tid] = 0.0f; }

    // PV accumulators: 8 rows x 8 dims (two float4 groups) per thread
    float4 olo[8], ohi[8];
#pragma unroll
    for (int i = 0; i < 8; i++) {
        olo[i] = make_float4(0.f, 0.f, 0.f, 0.f);
        ohi[i] = make_float4(0.f, 0.f, 0.f, 0.f);
    }

    const int sy = tid >> 3, sx = tid & 7;    // QK mapping: 32x8 thread grid
    const int ty = tid >> 4, tx = tid & 15;   // PV mapping: 16x16 thread grid

    int jmin = q0 - (WINDOW - 1);
    if (jmin < 0) jmin = 0;
    const int k0s = (jmin / BK) * BK;
    const int qhi = q0 + BQ - 1;
    const float scl = 0.08838834764831845f;   // 1/sqrt(128)

    for (int k0 = k0s; k0 <= qhi; k0 += BK) {
        __syncthreads();   // previous PV done with Vs/Ss

        // --- load K (rope'd) and V tiles ---
        for (int idx = tid * 4; idx < BK * D; idx += 256 * 4) {
            int r = idx >> 7, col = idx & 127;
            size_t gb = (((size_t)(b * S + k0 + r)) * HK + hk) * D + col;
            *(float4*)(Ks + r * KS_STRIDE + col) = *(const float4*)(g_kr + gb);
            *(float4*)(Vs + r * VS_STRIDE + col) = *(const float4*)(value + gb);
        }
        __syncthreads();

        // --- QK^T: each thread computes 4 rows x 8 keys ---
        float acc[4][8];
#pragma unroll
        for (int rr = 0; rr < 4; rr++)
#pragma unroll
            for (int cc = 0; cc < 8; cc++) acc[rr][cc] = 0.0f;

#pragma unroll 2
        for (int kk = 0; kk < D; kk += 4) {
            float4 qf[4], kf[8];
#pragma unroll
            for (int rr = 0; rr < 4; rr++)
                qf[rr] = *(const float4*)(Qs + (sy * 4 + rr) * QS_STRIDE + kk);
#pragma unroll
            for (int cc = 0; cc < 8; cc++)
                kf[cc] = *(const float4*)(Ks + (sx + cc * 8) * KS_STRIDE + kk);
#pragma unroll
            for (int rr = 0; rr < 4; rr++)
#pragma unroll
                for (int cc = 0; cc < 8; cc++) {
                    acc[rr][cc] += qf[rr].x * kf[cc].x;
                    acc[rr][cc] += qf[rr].y * kf[cc].y;
                    acc[rr][cc] += qf[rr].z * kf[cc].z;
                    acc[rr][cc] += qf[rr].w * kf[cc].w;
                }
        }

        // scale + sliding-window causal mask, store scores
#pragma unroll
        for (int rr = 0; rr < 4; rr++) {
            int r = sy * 4 + rr;
            int i = q0 + (r & (BQ - 1));
#pragma unroll
            for (int cc = 0; cc < 8; cc++) {
                int j = k0 + sx + cc * 8;
                float v = acc[rr][cc] * scl;
                if (j > i || (i - j) >= WINDOW) v = -1e30f;
                Ss[r * SS_STRIDE + sx + cc * 8] = v;
            }
        }
        __syncthreads();

        // --- online softmax: one thread per row ---
        if (tid < ROWS) {
            float m_old = rowm[tid];
            float* srow = Ss + tid * SS_STRIDE;
            float tm = -1e30f;
#pragma unroll 8
            for (int c = 0; c < BK; c++) tm = fmaxf(tm, srow[c]);
            float nm = fmaxf(m_old, tm);
            float sum = 0.0f;
#pragma unroll 8
            for (int c = 0; c < BK; c++) {
                float p = __expf(srow[c] - nm);
                srow[c] = p;
                sum += p;
            }
            float sc = __expf(m_old - nm);
            rowl[tid] = rowl[tid] * sc + sum;
            rowm[tid] = nm;
            rsc[tid]  = sc;
        }
        __syncthreads();

        // --- rescale O, then P@V ---
#pragma unroll
        for (int rr = 0; rr < 8; rr++) {
            float s = rsc[ty * 8 + rr];
            olo[rr].x *= s; olo[rr].y *= s; olo[rr].z *= s; olo[rr].w *= s;
            ohi[rr].x *= s; ohi[rr].y *= s; ohi[rr].z *= s; ohi[rr].w *= s;
        }
#pragma unroll 2
        for (int kk = 0; kk < BK; kk++) {
            float4 vlo = *(const float4*)(Vs + kk * VS_STRIDE + tx * 4);
            float4 vhi = *(const float4*)(Vs + kk * VS_STRIDE + 64 + tx * 4);
#pragma unroll
            for (int rr = 0; rr < 8; rr++) {
                float p = Ss[(ty * 8 + rr) * SS_STRIDE + kk];
                olo[rr].x += p * vlo.x; olo[rr].y += p * vlo.y;
                olo[rr].z += p * vlo.z; olo[rr].w += p * vlo.w;
                ohi[rr].x += p * vhi.x; ohi[rr].y += p * vhi.y;
                ohi[rr].z += p * vhi.z; ohi[rr].w += p * vhi.w;
            }
        }
    }

    // --- epilogue: normalize and write out ---
#pragma unroll
    for (int rr = 0; rr < 8; rr++) {
        int r = ty * 8 + rr;
        float inv = 1.0f / rowl[r];
        int i  = q0 + (r & (BQ - 1));
        int hq = hk * G + (r >> 5);
        float* ob = out + (((size_t)(b * S + i)) * HQ + hq) * D;
        float4 a = olo[rr], c = ohi[rr];
        a.x *= inv; a.y *= inv; a.z *= inv; a.w *= inv;
        c.x *= inv; c.y *= inv; c.z *= inv; c.w *= inv;
        *(float4*)(ob + tx * 4)      = a;
        *(float4*)(ob + 64 + tx * 4) = c;
    }
}

// ---------------------------------------------------------------------------
extern "C" void kernel_launch(void* const* d_in, const int* in_sizes, int n_in,
                              void* d_out, int out_size) {
    const float* q   = (const float*)d_in[0];
    const float* k   = (const float*)d_in[1];
    const float* v   = (const float*)d_in[2];
    const int*   pos = (const int*)d_in[3];
    float* out = (float*)d_out;

    const int smem_bytes =
        (ROWS * QS_STRIDE + BK * KS_STRIDE + BK * VS_STRIDE +
         ROWS * SS_STRIDE + 3 * ROWS) * (int)sizeof(float);
    cudaFuncSetAttribute(attn_kernel,
                         cudaFuncAttributeMaxDynamicSharedMemorySize,
                         smem_bytes);

    rope_kernel<<<B * S, 256>>>(q, k, pos);

    dim3 grid(S / BQ, HK, B);
    attn_kernel<<<grid, 256, smem_bytes>>>(v, out);
}

// round 4
// speedup vs baseline: 1.4986x; 1.4974x over previous
#include <cuda_runtime.h>
#include <math.h>
#include <stdint.h>

#define NB 2
#define NS 2048
#define NHQ 32
#define NHK 8
#define ND 128
#define NG 4
#define WIN 1024

// rope'd K scratch (allocation-free rule -> device global)
__device__ float g_kr[(size_t)NB * NHK * NS * ND];

__device__ __forceinline__ float ex2f(float x) {
    float r; asm("ex2.approx.ftz.f32 %0,%1;" : "=f"(r) : "f"(x)); return r;
}
__device__ __forceinline__ uint32_t f2tf(float x) {
    uint32_t r; asm("cvt.rna.tf32.f32 %0,%1;" : "=r"(r) : "f"(x)); return r;
}
__device__ __forceinline__ void split_tf32(float x, uint32_t& hi, uint32_t& lo) {
    uint32_t h; asm("cvt.rna.tf32.f32 %0,%1;" : "=r"(h) : "f"(x));
    float hf = __uint_as_float(h);
    uint32_t l; asm("cvt.rna.tf32.f32 %0,%1;" : "=r"(l) : "f"(x - hf));
    hi = h; lo = l;
}
__device__ __forceinline__ void mma_tf32(float* d, const uint32_t* a, const uint32_t* b) {
    asm volatile(
        "mma.sync.aligned.m16n8k8.row.col.f32.tf32.tf32.f32 "
        "{%0,%1,%2,%3},{%4,%5,%6,%7},{%8,%9},{%0,%1,%2,%3};"
        : "+f"(d[0]), "+f"(d[1]), "+f"(d[2]), "+f"(d[3])
        : "r"(a[0]), "r"(a[1]), "r"(a[2]), "r"(a[3]), "r"(b[0]), "r"(b[1]));
}
__device__ __forceinline__ uint32_t cvta(const void* p) {
    return (uint32_t)__cvta_generic_to_shared(p);
}
__device__ __forceinline__ void cpa(uint32_t d, const float* s) {
    asm volatile("cp.async.cg.shared.global [%0],[%1],16;" :: "r"(d), "l"(s));
}

// ---------------------------------------------------------------------------
// prep: rope K -> g_kr[b][hk][s][d]
// ---------------------------------------------------------------------------
__global__ void prep_kernel(const float* __restrict__ key, const int* __restrict__ pos) {
    const int k0 = blockIdx.x * 64, hk = blockIdx.y, b = blockIdx.z;
    const int tid = threadIdx.x;
#pragma unroll
    for (int i = 0; i < 16; i++) {
        int idx = tid + i * 256;
        int kl = idx >> 6, dp = idx & 63;
        int token = b * NS + k0 + kl;
        float ps = (float)pos[token];
        float invf = powf(10000.0f, -((float)dp) / 64.0f);
        float sn, cs; sincosf(ps * invf, &sn, &cs);
        const float* kp = key + (size_t)token * (NHK * ND) + hk * ND;
        float x1 = kp[dp], x2 = kp[dp + 64];
        float* ko = g_kr + ((size_t)(b * NHK + hk) * NS + k0 + kl) * ND;
        ko[dp]      = x1 * cs - x2 * sn;
        ko[dp + 64] = x2 * cs + x1 * sn;
    }
}

// ---------------------------------------------------------------------------
// attention: block = (16 queries, hk, b); 8 warps = 4 heads x 2 key-halves
// ---------------------------------------------------------------------------
__global__ void __launch_bounds__(256, 1)
attn_kernel(const float* __restrict__ query, const float* __restrict__ value,
            const int* __restrict__ pos, float* __restrict__ out) {
    extern __shared__ float smf[];
    float* Qs  = smf;             // 64 x 132 (later reused as merged-O buffer)
    float* Kst = smf + 8448;      // 2 x 64 x 132
    float* Vst = smf + 25344;     // 2 x 64 x 132
    float* Ps  = smf + 42240;     // 64 x 68  (sincos table / P tile / m,l xchg)

    const int qt = blockIdx.x, hk = blockIdx.y, b = blockIdx.z;
    const int q0 = qt * 16, tid = threadIdx.x;
    const int w = tid >> 5, lane = tid & 31;
    const int h = w & 3, kh = w >> 2;
    const int lr = lane >> 2, lc = lane & 3;
    const float CF = 1.4426950408889634f * 0.08838834764831845f; // log2e/sqrt(D)

    // phase A: sincos table (16 q x 64 pairs)
#pragma unroll
    for (int i = 0; i < 4; i++) {
        int idx = tid + i * 256;
        int qi = idx >> 6, dp = idx & 63;
        float ps = (float)pos[b * NS + q0 + qi];
        float invf = powf(10000.0f, -((float)dp) / 64.0f);
        float sn, cs; sincosf(ps * invf, &sn, &cs);
        Ps[idx] = cs; Ps[1024 + idx] = sn;
    }
    __syncthreads();
    // phase B: rope + scale Q -> Qs (row = head*16 + qi)
#pragma unroll
    for (int i = 0; i < 16; i++) {
        int idx = tid + i * 256;
        int row = idx >> 6, dp = idx & 63;
        int qi = row & 15, hh = row >> 4;
        const float* qp = query + ((size_t)(b * NS + q0 + qi) * NHQ + (hk * NG + hh)) * ND;
        float x1 = qp[dp], x2 = qp[dp + 64];
        float cs = Ps[qi * 64 + dp], sn = Ps[1024 + qi * 64 + dp];
        Qs[row * 132 + dp]      = (x1 * cs - x2 * sn) * CF;
        Qs[row * 132 + dp + 64] = (x2 * cs + x1 * sn) * CF;
    }

    int jmin = q0 - (WIN - 1); if (jmin < 0) jmin = 0; jmin &= ~63;
    const int nt = (q0 + 15 - jmin) / 64 + 1;

    const float* kgb = g_kr + (size_t)(b * NHK + hk) * NS * ND;
    const float* vgb = value + (size_t)b * NS * NHK * ND + (size_t)hk * ND;

    // prefetch tile 0
#pragma unroll
    for (int i = 0; i < 8; i++) {
        int idx = tid + i * 256;
        int r = idx >> 5, c4 = (idx & 31) * 4;
        cpa(cvta(Kst + r * 132 + c4), kgb + (size_t)(jmin + r) * ND + c4);
        cpa(cvta(Vst + r * 132 + c4), vgb + (size_t)(jmin + r) * NHK * ND + c4);
    }
    asm volatile("cp.async.commit_group;");

    float oacc[16][4];
#pragma unroll
    for (int nb = 0; nb < 16; nb++)
#pragma unroll
        for (int e = 0; e < 4; e++) oacc[nb][e] = 0.0f;
    float mcur0 = -1e30f, mcur1 = -1e30f, lcur0 = 0.0f, lcur1 = 0.0f;

    for (int t = 0; t < nt; t++) {
        const int k0 = jmin + t * 64;
        __syncthreads();                 // prior compute done before refilling buf
        if (t + 1 < nt) {
            int kn = k0 + 64, bn = (t + 1) & 1;
#pragma unroll
            for (int i = 0; i < 8; i++) {
                int idx = tid + i * 256;
                int r = idx >> 5, c4 = (idx & 31) * 4;
                cpa(cvta(Kst + bn * 8448 + r * 132 + c4), kgb + (size_t)(kn + r) * ND + c4);
                cpa(cvta(Vst + bn * 8448 + r * 132 + c4), vgb + (size_t)(kn + r) * NHK * ND + c4);
            }
            asm volatile("cp.async.commit_group;");
            asm volatile("cp.async.wait_group 1;");
        } else {
            asm volatile("cp.async.wait_group 0;");
        }
        __syncthreads();

        const float* K = Kst + (t & 1) * 8448;
        const float* V = Vst + (t & 1) * 8448;

        // ---- QK^T, 3xTF32 ----
        float sacc[4][4];
#pragma unroll
        for (int nb = 0; nb < 4; nb++)
#pragma unroll
            for (int e = 0; e < 4; e++) sacc[nb][e] = 0.0f;

#pragma unroll
        for (int c = 0; c < 16; c++) {
            uint32_t ah[4], al[4];
            split_tf32(Qs[(h * 16 + lr) * 132 + c * 8 + lc],         ah[0], al[0]);
            split_tf32(Qs[(h * 16 + lr + 8) * 132 + c * 8 + lc],     ah[1], al[1]);
            split_tf32(Qs[(h * 16 + lr) * 132 + c * 8 + lc + 4],     ah[2], al[2]);
            split_tf32(Qs[(h * 16 + lr + 8) * 132 + c * 8 + lc + 4], ah[3], al[3]);
#pragma unroll
            for (int nb = 0; nb < 4; nb++) {
                int krow = kh * 32 + nb * 8 + lr;
                uint32_t bh[2], bl[2];
                split_tf32(K[krow * 132 + c * 8 + lc],     bh[0], bl[0]);
                split_tf32(K[krow * 132 + c * 8 + lc + 4], bh[1], bl[1]);
                mma_tf32(sacc[nb], ah, bh);
                mma_tf32(sacc[nb], al, bh);
                mma_tf32(sacc[nb], ah, bl);
            }
        }

        // ---- mask ----
        const int i0 = q0 + lr, i1 = i0 + 8;
        if (!((k0 + 63 <= q0) && (q0 + 15 - k0 < WIN))) {
#pragma unroll
            for (int nb = 0; nb < 4; nb++) {
                int j0 = k0 + kh * 32 + nb * 8 + 2 * lc;
                if (j0 > i0     || i0 - j0 >= WIN)     sacc[nb][0] = -1e38f;
                if (j0 + 1 > i0 || i0 - j0 - 1 >= WIN) sacc[nb][1] = -1e38f;
                if (j0 > i1     || i1 - j0 >= WIN)     sacc[nb][2] = -1e38f;
                if (j0 + 1 > i1 || i1 - j0 - 1 >= WIN) sacc[nb][3] = -1e38f;
            }
        }

        // ---- online softmax (per warp, rows i0/i1) ----
        float r0 = -1e38f, r1 = -1e38f;
#pragma unroll
        for (int nb = 0; nb < 4; nb++) {
            r0 = fmaxf(r0, fmaxf(sacc[nb][0], sacc[nb][1]));
            r1 = fmaxf(r1, fmaxf(sacc[nb][2], sacc[nb][3]));
        }
        r0 = fmaxf(r0, __shfl_xor_sync(0xffffffffu, r0, 1));
        r0 = fmaxf(r0, __shfl_xor_sync(0xffffffffu, r0, 2));
        r1 = fmaxf(r1, __shfl_xor_sync(0xffffffffu, r1, 1));
        r1 = fmaxf(r1, __shfl_xor_sync(0xffffffffu, r1, 2));
        float mn0 = fmaxf(mcur0, r0), mn1 = fmaxf(mcur1, r1);
        float f0 = ex2f(mcur0 - mn0), f1 = ex2f(mcur1 - mn1);
        mcur0 = mn0; mcur1 = mn1;
        lcur0 *= f0; lcur1 *= f1;
        float s0 = 0.0f, s1 = 0.0f;
#pragma unroll
        for (int nb = 0; nb < 4; nb++) {
            float p00 = ex2f(sacc[nb][0] - mn0), p01 = ex2f(sacc[nb][1] - mn0);
            float p10 = ex2f(sacc[nb][2] - mn1), p11 = ex2f(sacc[nb][3] - mn1);
            s0 += p00 + p01; s1 += p10 + p11;
            int col = kh * 32 + nb * 8 + 2 * lc;
            *(float2*)&Ps[(h * 16 + lr) * 68 + col]     = make_float2(p00, p01);
            *(float2*)&Ps[(h * 16 + lr + 8) * 68 + col] = make_float2(p10, p11);
        }
        lcur0 += s0; lcur1 += s1;
#pragma unroll
        for (int nb = 0; nb < 16; nb++) {
            oacc[nb][0] *= f0; oacc[nb][1] *= f0;
            oacc[nb][2] *= f1; oacc[nb][3] *= f1;
        }
        __syncwarp();

        // ---- P @ V (partial over this warp's 32 keys) ----
#pragma unroll
        for (int kc = 0; kc < 4; kc++) {
            uint32_t ap[4];
            ap[0] = f2tf(Ps[(h * 16 + lr) * 68 + kh * 32 + kc * 8 + lc]);
            ap[1] = f2tf(Ps[(h * 16 + lr + 8) * 68 + kh * 32 + kc * 8 + lc]);
            ap[2] = f2tf(Ps[(h * 16 + lr) * 68 + kh * 32 + kc * 8 + lc + 4]);
            ap[3] = f2tf(Ps[(h * 16 + lr + 8) * 68 + kh * 32 + kc * 8 + lc + 4]);
#pragma unroll
            for (int nb = 0; nb < 16; nb++) {
                uint32_t bv[2];
                bv[0] = f2tf(V[(kh * 32 + kc * 8 + lc) * 132 + nb * 8 + lr]);
                bv[1] = f2tf(V[(kh * 32 + kc * 8 + lc + 4) * 132 + nb * 8 + lr]);
                mma_tf32(oacc[nb], ap, bv);
            }
        }
    }

    // ---- epilogue: reduce l over lane quads, merge key-halves, store ----
    lcur0 += __shfl_xor_sync(0xffffffffu, lcur0, 1);
    lcur0 += __shfl_xor_sync(0xffffffffu, lcur0, 2);
    lcur1 += __shfl_xor_sync(0xffffffffu, lcur1, 1);
    lcur1 += __shfl_xor_sync(0xffffffffu, lcur1, 2);
    __syncthreads();   // done with Qs (QK) and Ps (PV)

    if (kh == 1) {
        if (lc == 0) {
            Ps[h * 16 + lr] = mcur0;      Ps[h * 16 + lr + 8] = mcur1;
            Ps[64 + h * 16 + lr] = lcur0; Ps[64 + h * 16 + lr + 8] = lcur1;
        }
#pragma unroll
        for (int nb = 0; nb < 16; nb++) {
            int col = nb * 8 + 2 * lc;
            *(float2*)&Qs[(h * 16 + lr) * 132 + col]     = make_float2(oacc[nb][0], oacc[nb][1]);
            *(float2*)&Qs[(h * 16 + lr + 8) * 132 + col] = make_float2(oacc[nb][2], oacc[nb][3]);
        }
    }
    __syncthreads();
    if (kh == 0) {
        float m1a = Ps[h * 16 + lr],      m1b = Ps[h * 16 + lr + 8];
        float l1a = Ps[64 + h * 16 + lr], l1b = Ps[64 + h * 16 + lr + 8];
        float mfa = fmaxf(mcur0, m1a), mfb = fmaxf(mcur1, m1b);
        float a0 = ex2f(mcur0 - mfa), b0 = ex2f(m1a - mfa);
        float a1 = ex2f(mcur1 - mfb), b1 = ex2f(m1b - mfb);
        float li0 = 1.0f / (lcur0 * a0 + l1a * b0);
        float li1 = 1.0f / (lcur1 * a1 + l1b * b1);
#pragma unroll
        for (int nb = 0; nb < 16; nb++) {
            int col = nb * 8 + 2 * lc;
            float2 o1 = *(float2*)&Qs[(h * 16 + lr) * 132 + col];
            float2 o2 = *(float2*)&Qs[(h * 16 + lr + 8) * 132 + col];
            o1.x = (oacc[nb][0] * a0 + o1.x * b0) * li0;
            o1.y = (oacc[nb][1] * a0 + o1.y * b0) * li0;
            o2.x = (oacc[nb][2] * a1 + o2.x * b1) * li1;
            o2.y = (oacc[nb][3] * a1 + o2.y * b1) * li1;
            *(float2*)&Qs[(h * 16 + lr) * 132 + col]     = o1;
            *(float2*)&Qs[(h * 16 + lr + 8) * 132 + col] = o2;
        }
    }
    __syncthreads();
#pragma unroll
    for (int i = 0; i < 8; i++) {
        int idx = tid + i * 256;
        int hh = idx >> 9, qi = (idx >> 5) & 15, d4 = (idx & 31) * 4;
        float4 val = *(float4*)&Qs[(hh * 16 + qi) * 132 + d4];
        *(float4*)&out[((size_t)(b * NS + q0 + qi) * NHQ + hk * NG + hh) * ND + d4] = val;
    }
}

// ---------------------------------------------------------------------------
extern "C" void kernel_launch(void* const* d_in, const int* in_sizes, int n_in,
                              void* d_out, int out_size) {
    const float* q   = (const float*)d_in[0];
    const float* k   = (const float*)d_in[1];
    const float* v   = (const float*)d_in[2];
    const int*   pos = (const int*)d_in[3];
    float* out = (float*)d_out;

    dim3 gp(NS / 64, NHK, NB);
    prep_kernel<<<gp, 256>>>(k, pos);

    const int smem = 46592 * 4;
    cudaFuncSetAttribute(attn_kernel,
                         cudaFuncAttributeMaxDynamicSharedMemorySize, smem);
    dim3 ga(NS / 16, NHK, NB);
    attn_kernel<<<ga, 256, smem>>>(q, v, pos, out);
}

// round 5
// speedup vs baseline: 1.6635x; 1.1100x over previous
#include <cuda_runtime.h>
#include <math.h>
#include <stdint.h>

#define NB 2
#define NS 2048
#define NHQ 32
#define NHK 8
#define ND 128
#define NG 4
#define WIN 1024

// pre-split rope'd K (tf32 hi/lo) and pre-rounded V (tf32), [b][hk][s][d]
__device__ float g_khi[(size_t)NB * NHK * NS * ND];
__device__ float g_klo[(size_t)NB * NHK * NS * ND];
__device__ float g_vr [(size_t)NB * NHK * NS * ND];

__device__ __forceinline__ float ex2f(float x) {
    float r; asm("ex2.approx.ftz.f32 %0,%1;" : "=f"(r) : "f"(x)); return r;
}
__device__ __forceinline__ uint32_t f2tf(float x) {
    uint32_t r; asm("cvt.rna.tf32.f32 %0,%1;" : "=r"(r) : "f"(x)); return r;
}
__device__ __forceinline__ void split_tf32(float x, uint32_t& hi, uint32_t& lo) {
    uint32_t h; asm("cvt.rna.tf32.f32 %0,%1;" : "=r"(h) : "f"(x));
    float hf = __uint_as_float(h);
    uint32_t l; asm("cvt.rna.tf32.f32 %0,%1;" : "=r"(l) : "f"(x - hf));
    hi = h; lo = l;
}
__device__ __forceinline__ void mma_tf32(float* d, const uint32_t* a, const uint32_t* b) {
    asm volatile(
        "mma.sync.aligned.m16n8k8.row.col.f32.tf32.tf32.f32 "
        "{%0,%1,%2,%3},{%4,%5,%6,%7},{%8,%9},{%0,%1,%2,%3};"
        : "+f"(d[0]), "+f"(d[1]), "+f"(d[2]), "+f"(d[3])
        : "r"(a[0]), "r"(a[1]), "r"(a[2]), "r"(a[3]), "r"(b[0]), "r"(b[1]));
}
__device__ __forceinline__ uint32_t cvta(const void* p) {
    return (uint32_t)__cvta_generic_to_shared(p);
}
__device__ __forceinline__ void cpa(uint32_t d, const float* s) {
    asm volatile("cp.async.cg.shared.global [%0],[%1],16;" :: "r"(d), "l"(s));
}
#define COMMIT()  asm volatile("cp.async.commit_group;")
#define WAIT2()   asm volatile("cp.async.wait_group 2;")
#define WAIT0()   asm volatile("cp.async.wait_group 0;")

// smem offsets (floats)
#define QHI_OFF 0
#define QLO_OFF 8448
#define KH_OFF  16896   /* + buf*8448 */
#define KL_OFF  33792
#define V_OFF   42240
#define PS_OFF  50688
#define ML_OFF  55040
#define SMEM_FLOATS 55168

// ---------------------------------------------------------------------------
// prep: rope K -> split tf32 hi/lo; V -> tf32 round; layout [b][hk][s][d]
// ---------------------------------------------------------------------------
__global__ void prep_kernel(const float* __restrict__ key,
                            const float* __restrict__ value,
                            const int* __restrict__ pos) {
    const int k0 = blockIdx.x * 64, hk = blockIdx.y, b = blockIdx.z;
    const int tid = threadIdx.x;
    // K: rope + split
#pragma unroll
    for (int i = 0; i < 16; i++) {
        int idx = tid + i * 256;
        int kl = idx >> 6, dp = idx & 63;
        int token = b * NS + k0 + kl;
        float ps = (float)pos[token];
        float invf = powf(10000.0f, -((float)dp) / 64.0f);
        float sn, cs; sincosf(ps * invf, &sn, &cs);
        const float* kp = key + (size_t)token * (NHK * ND) + hk * ND;
        float x1 = kp[dp], x2 = kp[dp + 64];
        float o1 = x1 * cs - x2 * sn;
        float o2 = x2 * cs + x1 * sn;
        size_t ob = ((size_t)(b * NHK + hk) * NS + k0 + kl) * ND;
        uint32_t h, l;
        split_tf32(o1, h, l);
        g_khi[ob + dp] = __uint_as_float(h);
        g_klo[ob + dp] = __uint_as_float(l);
        split_tf32(o2, h, l);
        g_khi[ob + dp + 64] = __uint_as_float(h);
        g_klo[ob + dp + 64] = __uint_as_float(l);
    }
    // V: tf32 round + transpose head layout
#pragma unroll
    for (int i = 0; i < 8; i++) {
        int idx = tid + i * 256;
        int kl = idx >> 5, c4 = (idx & 31) * 4;
        int token = b * NS + k0 + kl;
        float4 v4 = *(const float4*)(value + (size_t)token * (NHK * ND) + hk * ND + c4);
        float4 o;
        o.x = __uint_as_float(f2tf(v4.x));
        o.y = __uint_as_float(f2tf(v4.y));
        o.z = __uint_as_float(f2tf(v4.z));
        o.w = __uint_as_float(f2tf(v4.w));
        *(float4*)(g_vr + ((size_t)(b * NHK + hk) * NS + k0 + kl) * ND + c4) = o;
    }
}

// ---------------------------------------------------------------------------
// attention: block = (16 queries, hk, b); 8 warps = 4 heads x 2 key-halves
// ---------------------------------------------------------------------------
__global__ void __launch_bounds__(256, 1)
attn_kernel(const float* __restrict__ query, const int* __restrict__ pos,
            float* __restrict__ out) {
    extern __shared__ float smf[];
    float*    Qs  = smf + QHI_OFF;               // fp32 O-merge reuse in epilogue
    uint32_t* QH  = (uint32_t*)(smf + QHI_OFF);  // 64 x 132 tf32 bits
    uint32_t* QL  = (uint32_t*)(smf + QLO_OFF);
    float*    Ps  = smf + PS_OFF;                // 64 x 68 (sincos / P / scratch)
    float*    ML  = smf + ML_OFF;                // m,l exchange

    const int qt = blockIdx.x, hk = blockIdx.y, b = blockIdx.z;
    const int q0 = qt * 16, tid = threadIdx.x;
    const int w = tid >> 5, lane = tid & 31;
    const int h = w & 3, kh = w >> 2;
    const int lr = lane >> 2, lc = lane & 3;
    const float CF = 1.4426950408889634f * 0.08838834764831845f; // log2e/sqrt(D)

    // phase A: sincos table (16 q x 64 pairs) in Ps
#pragma unroll
    for (int i = 0; i < 4; i++) {
        int idx = tid + i * 256;
        int qi = idx >> 6, dp = idx & 63;
        float ps = (float)pos[b * NS + q0 + qi];
        float invf = powf(10000.0f, -((float)dp) / 64.0f);
        float sn, cs; sincosf(ps * invf, &sn, &cs);
        Ps[idx] = cs; Ps[1024 + idx] = sn;
    }
    __syncthreads();
    // phase B: rope + scale + split Q -> QH/QL
#pragma unroll
    for (int i = 0; i < 16; i++) {
        int idx = tid + i * 256;
        int row = idx >> 6, dp = idx & 63;
        int qi = row & 15, hh = row >> 4;
        const float* qp = query + ((size_t)(b * NS + q0 + qi) * NHQ + (hk * NG + hh)) * ND;
        float x1 = qp[dp], x2 = qp[dp + 64];
        float cs = Ps[qi * 64 + dp], sn = Ps[1024 + qi * 64 + dp];
        float o1 = (x1 * cs - x2 * sn) * CF;
        float o2 = (x2 * cs + x1 * sn) * CF;
        uint32_t hi, lo;
        split_tf32(o1, hi, lo);
        QH[row * 132 + dp] = hi; QL[row * 132 + dp] = lo;
        split_tf32(o2, hi, lo);
        QH[row * 132 + dp + 64] = hi; QL[row * 132 + dp + 64] = lo;
    }
    __syncthreads();

    int jmin = q0 - (WIN - 1); if (jmin < 0) jmin = 0; jmin &= ~63;
    const int nt = (q0 + 15 - jmin) / 64 + 1;

    const float* khb = g_khi + (size_t)(b * NHK + hk) * NS * ND;
    const float* klb = g_klo + (size_t)(b * NHK + hk) * NS * ND;
    const float* vb  = g_vr  + (size_t)(b * NHK + hk) * NS * ND;

    const int cr = tid >> 5;            // copy row base (tid>>5), col (tid&31)*4
    const int cc4 = (tid & 31) * 4;

    // prologue: KH(0), KL(0), V(0) as three groups
#pragma unroll
    for (int i = 0; i < 8; i++)
        cpa(cvta(smf + KH_OFF + (cr + i * 8) * 132 + cc4), khb + (size_t)(jmin + cr + i * 8) * ND + cc4);
    COMMIT();
#pragma unroll
    for (int i = 0; i < 8; i++)
        cpa(cvta(smf + KL_OFF + (cr + i * 8) * 132 + cc4), klb + (size_t)(jmin + cr + i * 8) * ND + cc4);
    COMMIT();
#pragma unroll
    for (int i = 0; i < 8; i++)
        cpa(cvta(smf + V_OFF + (cr + i * 8) * 132 + cc4), vb + (size_t)(jmin + cr + i * 8) * ND + cc4);
    COMMIT();

    float oacc[16][4];
#pragma unroll
    for (int nb = 0; nb < 16; nb++)
#pragma unroll
        for (int e = 0; e < 4; e++) oacc[nb][e] = 0.0f;
    float mcur0 = -1e30f, mcur1 = -1e30f, lcur0 = 0.0f, lcur1 = 0.0f;

    for (int t = 0; t < nt; t++) {
        const int k0 = jmin + t * 64;

        // issue next KH (double-buffered)
        if (t + 1 < nt) {
            const float* src = khb + (size_t)(k0 + 64) * ND;
            uint32_t dst = cvta(smf + KH_OFF + ((t + 1) & 1) * 8448);
#pragma unroll
            for (int i = 0; i < 8; i++)
                cpa(dst + ((cr + i * 8) * 132 + cc4) * 4, src + (size_t)(cr + i * 8) * ND + cc4);
        }
        COMMIT();
        WAIT2();            // KH(t), KL(t) visible
        __syncthreads();

        const uint32_t* KH = (const uint32_t*)(smf + KH_OFF + (t & 1) * 8448);
        const uint32_t* KL = (const uint32_t*)(smf + KL_OFF);
        const uint32_t* Vu = (const uint32_t*)(smf + V_OFF);

        // ---- QK^T, 3xTF32 (all operands pre-converted) ----
        float sacc[4][4];
#pragma unroll
        for (int nb = 0; nb < 4; nb++)
#pragma unroll
            for (int e = 0; e < 4; e++) sacc[nb][e] = 0.0f;

#pragma unroll
        for (int c = 0; c < 16; c++) {
            uint32_t ah[4], al[4];
            ah[0] = QH[(h * 16 + lr) * 132 + c * 8 + lc];
            ah[1] = QH[(h * 16 + lr + 8) * 132 + c * 8 + lc];
            ah[2] = QH[(h * 16 + lr) * 132 + c * 8 + lc + 4];
            ah[3] = QH[(h * 16 + lr + 8) * 132 + c * 8 + lc + 4];
            al[0] = QL[(h * 16 + lr) * 132 + c * 8 + lc];
            al[1] = QL[(h * 16 + lr + 8) * 132 + c * 8 + lc];
            al[2] = QL[(h * 16 + lr) * 132 + c * 8 + lc + 4];
            al[3] = QL[(h * 16 + lr + 8) * 132 + c * 8 + lc + 4];
#pragma unroll
            for (int nb = 0; nb < 4; nb++) {
                int krow = kh * 32 + nb * 8 + lr;
                uint32_t bh[2], bl[2];
                bh[0] = KH[krow * 132 + c * 8 + lc];
                bh[1] = KH[krow * 132 + c * 8 + lc + 4];
                bl[0] = KL[krow * 132 + c * 8 + lc];
                bl[1] = KL[krow * 132 + c * 8 + lc + 4];
                mma_tf32(sacc[nb], ah, bh);
                mma_tf32(sacc[nb], al, bh);
                mma_tf32(sacc[nb], ah, bl);
            }
        }

        // ---- mask (registers) ----
        const int i0 = q0 + lr, i1 = i0 + 8;
        if (!((k0 + 63 <= q0) && (q0 + 15 - k0 < WIN))) {
#pragma unroll
            for (int nb = 0; nb < 4; nb++) {
                int j0 = k0 + kh * 32 + nb * 8 + 2 * lc;
                if (j0 > i0     || i0 - j0 >= WIN)     sacc[nb][0] = -1e38f;
                if (j0 + 1 > i0 || i0 - j0 - 1 >= WIN) sacc[nb][1] = -1e38f;
                if (j0 > i1     || i1 - j0 >= WIN)     sacc[nb][2] = -1e38f;
                if (j0 + 1 > i1 || i1 - j0 - 1 >= WIN) sacc[nb][3] = -1e38f;
            }
        }
        __syncthreads();    // all warps done reading KL(t)

        // issue next KL (single buffer, hidden by softmax+PV)
        if (t + 1 < nt) {
            const float* src = klb + (size_t)(k0 + 64) * ND;
#pragma unroll
            for (int i = 0; i < 8; i++)
                cpa(cvta(smf + KL_OFF + (cr + i * 8) * 132 + cc4), src + (size_t)(cr + i * 8) * ND + cc4);
        }
        COMMIT();
        WAIT2();            // V(t) visible
        __syncthreads();

        // ---- online softmax (per warp, rows i0/i1) ----
        float r0 = -1e38f, r1 = -1e38f;
#pragma unroll
        for (int nb = 0; nb < 4; nb++) {
            r0 = fmaxf(r0, fmaxf(sacc[nb][0], sacc[nb][1]));
            r1 = fmaxf(r1, fmaxf(sacc[nb][2], sacc[nb][3]));
        }
        r0 = fmaxf(r0, __shfl_xor_sync(0xffffffffu, r0, 1));
        r0 = fmaxf(r0, __shfl_xor_sync(0xffffffffu, r0, 2));
        r1 = fmaxf(r1, __shfl_xor_sync(0xffffffffu, r1, 1));
        r1 = fmaxf(r1, __shfl_xor_sync(0xffffffffu, r1, 2));
        float mn0 = fmaxf(mcur0, r0), mn1 = fmaxf(mcur1, r1);
        float f0 = ex2f(mcur0 - mn0), f1 = ex2f(mcur1 - mn1);
        mcur0 = mn0; mcur1 = mn1;
        lcur0 *= f0; lcur1 *= f1;
        float s0 = 0.0f, s1 = 0.0f;
#pragma unroll
        for (int nb = 0; nb < 4; nb++) {
            float p00 = ex2f(sacc[nb][0] - mn0), p01 = ex2f(sacc[nb][1] - mn0);
            float p10 = ex2f(sacc[nb][2] - mn1), p11 = ex2f(sacc[nb][3] - mn1);
            s0 += p00 + p01; s1 += p10 + p11;
            int col = kh * 32 + nb * 8 + 2 * lc;
            *(float2*)&Ps[(h * 16 + lr) * 68 + col]     = make_float2(p00, p01);
            *(float2*)&Ps[(h * 16 + lr + 8) * 68 + col] = make_float2(p10, p11);
        }
        lcur0 += s0; lcur1 += s1;
#pragma unroll
        for (int nb = 0; nb < 16; nb++) {
            oacc[nb][0] *= f0; oacc[nb][1] *= f0;
            oacc[nb][2] *= f1; oacc[nb][3] *= f1;
        }
        __syncwarp();

        // ---- P @ V ----
#pragma unroll
        for (int kc = 0; kc < 4; kc++) {
            uint32_t ap[4];
            ap[0] = f2tf(Ps[(h * 16 + lr) * 68 + kh * 32 + kc * 8 + lc]);
            ap[1] = f2tf(Ps[(h * 16 + lr + 8) * 68 + kh * 32 + kc * 8 + lc]);
            ap[2] = f2tf(Ps[(h * 16 + lr) * 68 + kh * 32 + kc * 8 + lc + 4]);
            ap[3] = f2tf(Ps[(h * 16 + lr + 8) * 68 + kh * 32 + kc * 8 + lc + 4]);
#pragma unroll
            for (int nb = 0; nb < 16; nb++) {
                uint32_t bv[2];
                bv[0] = Vu[(kh * 32 + kc * 8 + lc) * 132 + nb * 8 + lr];
                bv[1] = Vu[(kh * 32 + kc * 8 + lc + 4) * 132 + nb * 8 + lr];
                mma_tf32(oacc[nb], ap, bv);
            }
        }
        __syncthreads();    // all warps done reading V(t)

        // issue next V (single buffer, hidden by next QK)
        if (t + 1 < nt) {
            const float* src = vb + (size_t)(k0 + 64) * ND;
#pragma unroll
            for (int i = 0; i < 8; i++)
                cpa(cvta(smf + V_OFF + (cr + i * 8) * 132 + cc4), src + (size_t)(cr + i * 8) * ND + cc4);
        }
        COMMIT();
    }
    WAIT0();

    // ---- epilogue: reduce l over lane quads, merge key-halves, store ----
    lcur0 += __shfl_xor_sync(0xffffffffu, lcur0, 1);
    lcur0 += __shfl_xor_sync(0xffffffffu, lcur0, 2);
    lcur1 += __shfl_xor_sync(0xffffffffu, lcur1, 1);
    lcur1 += __shfl_xor_sync(0xffffffffu, lcur1, 2);
    __syncthreads();   // done with QH/QL and Ps

    if (kh == 1) {
        if (lc == 0) {
            ML[h * 16 + lr] = mcur0;      ML[h * 16 + lr + 8] = mcur1;
            ML[64 + h * 16 + lr] = lcur0; ML[64 + h * 16 + lr + 8] = lcur1;
        }
#pragma unroll
        for (int nb = 0; nb < 16; nb++) {
            int col = nb * 8 + 2 * lc;
            *(float2*)&Qs[(h * 16 + lr) * 132 + col]     = make_float2(oacc[nb][0], oacc[nb][1]);
            *(float2*)&Qs[(h * 16 + lr + 8) * 132 + col] = make_float2(oacc[nb][2], oacc[nb][3]);
        }
    }
    __syncthreads();
    if (kh == 0) {
        float m1a = ML[h * 16 + lr],      m1b = ML[h * 16 + lr + 8];
        float l1a = ML[64 + h * 16 + lr], l1b = ML[64 + h * 16 + lr + 8];
        float mfa = fmaxf(mcur0, m1a), mfb = fmaxf(mcur1, m1b);
        float a0 = ex2f(mcur0 - mfa), b0 = ex2f(m1a - mfa);
        float a1 = ex2f(mcur1 - mfb), b1 = ex2f(m1b - mfb);
        float li0 = 1.0f / (lcur0 * a0 + l1a * b0);
        float li1 = 1.0f / (lcur1 * a1 + l1b * b1);
#pragma unroll
        for (int nb = 0; nb < 16; nb++) {
            int col = nb * 8 + 2 * lc;
            float2 o1 = *(float2*)&Qs[(h * 16 + lr) * 132 + col];
            float2 o2 = *(float2*)&Qs[(h * 16 + lr + 8) * 132 + col];
            o1.x = (oacc[nb][0] * a0 + o1.x * b0) * li0;
            o1.y = (oacc[nb][1] * a0 + o1.y * b0) * li0;
            o2.x = (oacc[nb][2] * a1 + o2.x * b1) * li1;
            o2.y = (oacc[nb][3] * a1 + o2.y * b1) * li1;
            *(float2*)&Qs[(h * 16 + lr) * 132 + col]     = o1;
            *(float2*)&Qs[(h * 16 + lr + 8) * 132 + col] = o2;
        }
    }
    __syncthreads();
#pragma unroll
    for (int i = 0; i < 8; i++) {
        int idx = tid + i * 256;
        int hh = idx >> 9, qi = (idx >> 5) & 15, d4 = (idx & 31) * 4;
        float4 val = *(float4*)&Qs[(hh * 16 + qi) * 132 + d4];
        *(float4*)&out[((size_t)(b * NS + q0 + qi) * NHQ + hk * NG + hh) * ND + d4] = val;
    }
}

// ---------------------------------------------------------------------------
extern "C" void kernel_launch(void* const* d_in, const int* in_sizes, int n_in,
                              void* d_out, int out_size) {
    const float* q   = (const float*)d_in[0];
    const float* k   = (const float*)d_in[1];
    const float* v   = (const float*)d_in[2];
    const int*   pos = (const int*)d_in[3];
    float* out = (float*)d_out;

    dim3 gp(NS / 64, NHK, NB);
    prep_kernel<<<gp, 256>>>(k, v, pos);

    const int smem = SMEM_FLOATS * 4;
    cudaFuncSetAttribute(attn_kernel,
                         cudaFuncAttributeMaxDynamicSharedMemorySize, smem);
    dim3 ga(NS / 16, NHK, NB);
    attn_kernel<<<ga, 256, smem>>>(q, pos, out);
}

// round 6
// speedup vs baseline: 1.6650x; 1.0009x over previous
#include <cuda_runtime.h>
#include <math.h>
#include <stdint.h>

#define NB 2
#define NS 2048
#define NHQ 32
#define NHK 8
#define ND 128
#define NG 4
#define WIN 1024

// pre-split rope'd K (tf32 hi/lo) and pre-rounded V (tf32), [b][hk][s][d]
__device__ float g_khi[(size_t)NB * NHK * NS * ND];
__device__ float g_klo[(size_t)NB * NHK * NS * ND];
__device__ float g_vr [(size_t)NB * NHK * NS * ND];

__device__ __forceinline__ float ex2f(float x) {
    float r; asm("ex2.approx.ftz.f32 %0,%1;" : "=f"(r) : "f"(x)); return r;
}
__device__ __forceinline__ uint32_t f2tf(float x) {
    uint32_t r; asm("cvt.rna.tf32.f32 %0,%1;" : "=r"(r) : "f"(x)); return r;
}
__device__ __forceinline__ void split_tf32(float x, uint32_t& hi, uint32_t& lo) {
    uint32_t h; asm("cvt.rna.tf32.f32 %0,%1;" : "=r"(h) : "f"(x));
    float hf = __uint_as_float(h);
    uint32_t l; asm("cvt.rna.tf32.f32 %0,%1;" : "=r"(l) : "f"(x - hf));
    hi = h; lo = l;
}
__device__ __forceinline__ void mma_tf32(float* d, const uint32_t* a, const uint32_t* b) {
    asm volatile(
        "mma.sync.aligned.m16n8k8.row.col.f32.tf32.tf32.f32 "
        "{%0,%1,%2,%3},{%4,%5,%6,%7},{%8,%9},{%0,%1,%2,%3};"
        : "+f"(d[0]), "+f"(d[1]), "+f"(d[2]), "+f"(d[3])
        : "r"(a[0]), "r"(a[1]), "r"(a[2]), "r"(a[3]), "r"(b[0]), "r"(b[1]));
}
__device__ __forceinline__ uint32_t cvta(const void* p) {
    return (uint32_t)__cvta_generic_to_shared(p);
}
__device__ __forceinline__ void cpa(uint32_t d, const float* s) {
    asm volatile("cp.async.cg.shared.global [%0],[%1],16;" :: "r"(d), "l"(s));
}
#define COMMIT()  asm volatile("cp.async.commit_group;")
#define WAIT2()   asm volatile("cp.async.wait_group 2;")
#define WAIT0()   asm volatile("cp.async.wait_group 0;")

// smem offsets (floats)
#define QHI_OFF 0
#define QLO_OFF 8448
#define KH_OFF  16896   /* + buf*8448 */
#define KL_OFF  33792
#define V_OFF   42240
#define PS_OFF  50688
#define ML_OFF  55040
#define SMEM_FLOATS 55168

// ---------------------------------------------------------------------------
// prep: rope K -> split tf32 hi/lo; V -> tf32 round; layout [b][hk][s][d]
// ---------------------------------------------------------------------------
__global__ void prep_kernel(const float* __restrict__ key,
                            const float* __restrict__ value,
                            const int* __restrict__ pos) {
    const int k0 = blockIdx.x * 64, hk = blockIdx.y, b = blockIdx.z;
    const int tid = threadIdx.x;
    // K: rope + split
#pragma unroll
    for (int i = 0; i < 16; i++) {
        int idx = tid + i * 256;
        int kl = idx >> 6, dp = idx & 63;
        int token = b * NS + k0 + kl;
        float ps = (float)pos[token];
        float invf = powf(10000.0f, -((float)dp) / 64.0f);
        float sn, cs; sincosf(ps * invf, &sn, &cs);
        const float* kp = key + (size_t)token * (NHK * ND) + hk * ND;
        float x1 = kp[dp], x2 = kp[dp + 64];
        float o1 = x1 * cs - x2 * sn;
        float o2 = x2 * cs + x1 * sn;
        size_t ob = ((size_t)(b * NHK + hk) * NS + k0 + kl) * ND;
        uint32_t h, l;
        split_tf32(o1, h, l);
        g_khi[ob + dp] = __uint_as_float(h);
        g_klo[ob + dp] = __uint_as_float(l);
        split_tf32(o2, h, l);
        g_khi[ob + dp + 64] = __uint_as_float(h);
        g_klo[ob + dp + 64] = __uint_as_float(l);
    }
    // V: tf32 round + transpose head layout
#pragma unroll
    for (int i = 0; i < 8; i++) {
        int idx = tid + i * 256;
        int kl = idx >> 5, c4 = (idx & 31) * 4;
        int token = b * NS + k0 + kl;
        float4 v4 = *(const float4*)(value + (size_t)token * (NHK * ND) + hk * ND + c4);
        float4 o;
        o.x = __uint_as_float(f2tf(v4.x));
        o.y = __uint_as_float(f2tf(v4.y));
        o.z = __uint_as_float(f2tf(v4.z));
        o.w = __uint_as_float(f2tf(v4.w));
        *(float4*)(g_vr + ((size_t)(b * NHK + hk) * NS + k0 + kl) * ND + c4) = o;
    }
}

// ---------------------------------------------------------------------------
// attention: block = (16 queries, hk, b); 8 warps = 4 heads x 2 key-halves
// ---------------------------------------------------------------------------
__global__ void __launch_bounds__(256, 1)
attn_kernel(const float* __restrict__ query, const int* __restrict__ pos,
            float* __restrict__ out) {
    extern __shared__ float smf[];
    float*    Qs  = smf + QHI_OFF;               // fp32 O-merge reuse in epilogue
    uint32_t* QH  = (uint32_t*)(smf + QHI_OFF);  // 64 x 132 tf32 bits
    uint32_t* QL  = (uint32_t*)(smf + QLO_OFF);
    float*    Ps  = smf + PS_OFF;                // 64 x 68 (sincos / P / scratch)
    float*    ML  = smf + ML_OFF;                // m,l exchange

    const int qt = blockIdx.x, hk = blockIdx.y, b = blockIdx.z;
    const int q0 = qt * 16, tid = threadIdx.x;
    const int w = tid >> 5, lane = tid & 31;
    const int h = w & 3, kh = w >> 2;
    const int lr = lane >> 2, lc = lane & 3;
    const float CF = 1.4426950408889634f * 0.08838834764831845f; // log2e/sqrt(D)

    // phase A: sincos table (16 q x 64 pairs) in Ps
#pragma unroll
    for (int i = 0; i < 4; i++) {
        int idx = tid + i * 256;
        int qi = idx >> 6, dp = idx & 63;
        float ps = (float)pos[b * NS + q0 + qi];
        float invf = powf(10000.0f, -((float)dp) / 64.0f);
        float sn, cs; sincosf(ps * invf, &sn, &cs);
        Ps[idx] = cs; Ps[1024 + idx] = sn;
    }
    __syncthreads();
    // phase B: rope + scale + split Q -> QH/QL
#pragma unroll
    for (int i = 0; i < 16; i++) {
        int idx = tid + i * 256;
        int row = idx >> 6, dp = idx & 63;
        int qi = row & 15, hh = row >> 4;
        const float* qp = query + ((size_t)(b * NS + q0 + qi) * NHQ + (hk * NG + hh)) * ND;
        float x1 = qp[dp], x2 = qp[dp + 64];
        float cs = Ps[qi * 64 + dp], sn = Ps[1024 + qi * 64 + dp];
        float o1 = (x1 * cs - x2 * sn) * CF;
        float o2 = (x2 * cs + x1 * sn) * CF;
        uint32_t hi, lo;
        split_tf32(o1, hi, lo);
        QH[row * 132 + dp] = hi; QL[row * 132 + dp] = lo;
        split_tf32(o2, hi, lo);
        QH[row * 132 + dp + 64] = hi; QL[row * 132 + dp + 64] = lo;
    }
    __syncthreads();

    int jmin = q0 - (WIN - 1); if (jmin < 0) jmin = 0; jmin &= ~63;
    const int nt = (q0 + 15 - jmin) / 64 + 1;

    const float* khb = g_khi + (size_t)(b * NHK + hk) * NS * ND;
    const float* klb = g_klo + (size_t)(b * NHK + hk) * NS * ND;
    const float* vb  = g_vr  + (size_t)(b * NHK + hk) * NS * ND;

    const int cr = tid >> 5;            // copy row base (tid>>5), col (tid&31)*4
    const int cc4 = (tid & 31) * 4;

    // prologue: KH(0), KL(0), V(0) as three groups
#pragma unroll
    for (int i = 0; i < 8; i++)
        cpa(cvta(smf + KH_OFF + (cr + i * 8) * 132 + cc4), khb + (size_t)(jmin + cr + i * 8) * ND + cc4);
    COMMIT();
#pragma unroll
    for (int i = 0; i < 8; i++)
        cpa(cvta(smf + KL_OFF + (cr + i * 8) * 132 + cc4), klb + (size_t)(jmin + cr + i * 8) * ND + cc4);
    COMMIT();
#pragma unroll
    for (int i = 0; i < 8; i++)
        cpa(cvta(smf + V_OFF + (cr + i * 8) * 132 + cc4), vb + (size_t)(jmin + cr + i * 8) * ND + cc4);
    COMMIT();

    float oacc[16][4];
#pragma unroll
    for (int nb = 0; nb < 16; nb++)
#pragma unroll
        for (int e = 0; e < 4; e++) oacc[nb][e] = 0.0f;
    float mcur0 = -1e30f, mcur1 = -1e30f, lcur0 = 0.0f, lcur1 = 0.0f;

    for (int t = 0; t < nt; t++) {
        const int k0 = jmin + t * 64;

        // issue next KH (double-buffered)
        if (t + 1 < nt) {
            const float* src = khb + (size_t)(k0 + 64) * ND;
            uint32_t dst = cvta(smf + KH_OFF + ((t + 1) & 1) * 8448);
#pragma unroll
            for (int i = 0; i < 8; i++)
                cpa(dst + ((cr + i * 8) * 132 + cc4) * 4, src + (size_t)(cr + i * 8) * ND + cc4);
        }
        COMMIT();
        WAIT2();            // KH(t), KL(t) visible
        __syncthreads();

        const uint32_t* KH = (const uint32_t*)(smf + KH_OFF + (t & 1) * 8448);
        const uint32_t* KL = (const uint32_t*)(smf + KL_OFF);
        const uint32_t* Vu = (const uint32_t*)(smf + V_OFF);

        // ---- QK^T, 3xTF32 (all operands pre-converted) ----
        float sacc[4][4];
#pragma unroll
        for (int nb = 0; nb < 4; nb++)
#pragma unroll
            for (int e = 0; e < 4; e++) sacc[nb][e] = 0.0f;

#pragma unroll
        for (int c = 0; c < 16; c++) {
            uint32_t ah[4], al[4];
            ah[0] = QH[(h * 16 + lr) * 132 + c * 8 + lc];
            ah[1] = QH[(h * 16 + lr + 8) * 132 + c * 8 + lc];
            ah[2] = QH[(h * 16 + lr) * 132 + c * 8 + lc + 4];
            ah[3] = QH[(h * 16 + lr + 8) * 132 + c * 8 + lc + 4];
            al[0] = QL[(h * 16 + lr) * 132 + c * 8 + lc];
            al[1] = QL[(h * 16 + lr + 8) * 132 + c * 8 + lc];
            al[2] = QL[(h * 16 + lr) * 132 + c * 8 + lc + 4];
            al[3] = QL[(h * 16 + lr + 8) * 132 + c * 8 + lc + 4];
#pragma unroll
            for (int nb = 0; nb < 4; nb++) {
                int krow = kh * 32 + nb * 8 + lr;
                uint32_t bh[2], bl[2];
                bh[0] = KH[krow * 132 + c * 8 + lc];
                bh[1] = KH[krow * 132 + c * 8 + lc + 4];
                bl[0] = KL[krow * 132 + c * 8 + lc];
                bl[1] = KL[krow * 132 + c * 8 + lc + 4];
                mma_tf32(sacc[nb], ah, bh);
                mma_tf32(sacc[nb], al, bh);
                mma_tf32(sacc[nb], ah, bl);
            }
        }

        // ---- mask (registers) ----
        const int i0 = q0 + lr, i1 = i0 + 8;
        if (!((k0 + 63 <= q0) && (q0 + 15 - k0 < WIN))) {
#pragma unroll
            for (int nb = 0; nb < 4; nb++) {
                int j0 = k0 + kh * 32 + nb * 8 + 2 * lc;
                if (j0 > i0     || i0 - j0 >= WIN)     sacc[nb][0] = -1e38f;
                if (j0 + 1 > i0 || i0 - j0 - 1 >= WIN) sacc[nb][1] = -1e38f;
                if (j0 > i1     || i1 - j0 >= WIN)     sacc[nb][2] = -1e38f;
                if (j0 + 1 > i1 || i1 - j0 - 1 >= WIN) sacc[nb][3] = -1e38f;
            }
        }
        __syncthreads();    // all warps done reading KL(t)

        // issue next KL (single buffer, hidden by softmax+PV)
        if (t + 1 < nt) {
            const float* src = klb + (size_t)(k0 + 64) * ND;
#pragma unroll
            for (int i = 0; i < 8; i++)
                cpa(cvta(smf + KL_OFF + (cr + i * 8) * 132 + cc4), src + (size_t)(cr + i * 8) * ND + cc4);
        }
        COMMIT();
        WAIT2();            // V(t) visible
        __syncthreads();

        // ---- online softmax (per warp, rows i0/i1) ----
        float r0 = -1e38f, r1 = -1e38f;
#pragma unroll
        for (int nb = 0; nb < 4; nb++) {
            r0 = fmaxf(r0, fmaxf(sacc[nb][0], sacc[nb][1]));
            r1 = fmaxf(r1, fmaxf(sacc[nb][2], sacc[nb][3]));
        }
        r0 = fmaxf(r0, __shfl_xor_sync(0xffffffffu, r0, 1));
        r0 = fmaxf(r0, __shfl_xor_sync(0xffffffffu, r0, 2));
        r1 = fmaxf(r1, __shfl_xor_sync(0xffffffffu, r1, 1));
        r1 = fmaxf(r1, __shfl_xor_sync(0xffffffffu, r1, 2));
        float mn0 = fmaxf(mcur0, r0), mn1 = fmaxf(mcur1, r1);
        float f0 = ex2f(mcur0 - mn0), f1 = ex2f(mcur1 - mn1);
        mcur0 = mn0; mcur1 = mn1;
        lcur0 *= f0; lcur1 *= f1;
        float s0 = 0.0f, s1 = 0.0f;
#pragma unroll
        for (int nb = 0; nb < 4; nb++) {
            float p00 = ex2f(sacc[nb][0] - mn0), p01 = ex2f(sacc[nb][1] - mn0);
            float p10 = ex2f(sacc[nb][2] - mn1), p11 = ex2f(sacc[nb][3] - mn1);
            s0 += p00 + p01; s1 += p10 + p11;
            int col = kh * 32 + nb * 8 + 2 * lc;
            *(float2*)&Ps[(h * 16 + lr) * 68 + col]     = make_float2(p00, p01);
            *(float2*)&Ps[(h * 16 + lr + 8) * 68 + col] = make_float2(p10, p11);
        }
        lcur0 += s0; lcur1 += s1;
#pragma unroll
        for (int nb = 0; nb < 16; nb++) {
            oacc[nb][0] *= f0; oacc[nb][1] *= f0;
            oacc[nb][2] *= f1; oacc[nb][3] *= f1;
        }
        __syncwarp();

        // ---- P @ V ----
#pragma unroll
        for (int kc = 0; kc < 4; kc++) {
            uint32_t ap[4];
            ap[0] = f2tf(Ps[(h * 16 + lr) * 68 + kh * 32 + kc * 8 + lc]);
            ap[1] = f2tf(Ps[(h * 16 + lr + 8) * 68 + kh * 32 + kc * 8 + lc]);
            ap[2] = f2tf(Ps[(h * 16 + lr) * 68 + kh * 32 + kc * 8 + lc + 4]);
            ap[3] = f2tf(Ps[(h * 16 + lr + 8) * 68 + kh * 32 + kc * 8 + lc + 4]);
#pragma unroll
            for (int nb = 0; nb < 16; nb++) {
                uint32_t bv[2];
                bv[0] = Vu[(kh * 32 + kc * 8 + lc) * 132 + nb * 8 + lr];
                bv[1] = Vu[(kh * 32 + kc * 8 + lc + 4) * 132 + nb * 8 + lr];
                mma_tf32(oacc[nb], ap, bv);
            }
        }
        __syncthreads();    // all warps done reading V(t)

        // issue next V (single buffer, hidden by next QK)
        if (t + 1 < nt) {
            const float* src = vb + (size_t)(k0 + 64) * ND;
#pragma unroll
            for (int i = 0; i < 8; i++)
                cpa(cvta(smf + V_OFF + (cr + i * 8) * 132 + cc4), src + (size_t)(cr + i * 8) * ND + cc4);
        }
        COMMIT();
    }
    WAIT0();

    // ---- epilogue: reduce l over lane quads, merge key-halves, store ----
    lcur0 += __shfl_xor_sync(0xffffffffu, lcur0, 1);
    lcur0 += __shfl_xor_sync(0xffffffffu, lcur0, 2);
    lcur1 += __shfl_xor_sync(0xffffffffu, lcur1, 1);
    lcur1 += __shfl_xor_sync(0xffffffffu, lcur1, 2);
    __syncthreads();   // done with QH/QL and Ps

    if (kh == 1) {
        if (lc == 0) {
            ML[h * 16 + lr] = mcur0;      ML[h * 16 + lr + 8] = mcur1;
            ML[64 + h * 16 + lr] = lcur0; ML[64 + h * 16 + lr + 8] = lcur1;
        }
#pragma unroll
        for (int nb = 0; nb < 16; nb++) {
            int col = nb * 8 + 2 * lc;
            *(float2*)&Qs[(h * 16 + lr) * 132 + col]     = make_float2(oacc[nb][0], oacc[nb][1]);
            *(float2*)&Qs[(h * 16 + lr + 8) * 132 + col] = make_float2(oacc[nb][2], oacc[nb][3]);
        }
    }
    __syncthreads();
    if (kh == 0) {
        float m1a = ML[h * 16 + lr],      m1b = ML[h * 16 + lr + 8];
        float l1a = ML[64 + h * 16 + lr], l1b = ML[64 + h * 16 + lr + 8];
        float mfa = fmaxf(mcur0, m1a), mfb = fmaxf(mcur1, m1b);
        float a0 = ex2f(mcur0 - mfa), b0 = ex2f(m1a - mfa);
        float a1 = ex2f(mcur1 - mfb), b1 = ex2f(m1b - mfb);
        float li0 = 1.0f / (lcur0 * a0 + l1a * b0);
        float li1 = 1.0f / (lcur1 * a1 + l1b * b1);
#pragma unroll
        for (int nb = 0; nb < 16; nb++) {
            int col = nb * 8 + 2 * lc;
            float2 o1 = *(float2*)&Qs[(h * 16 + lr) * 132 + col];
            float2 o2 = *(float2*)&Qs[(h * 16 + lr + 8) * 132 + col];
            o1.x = (oacc[nb][0] * a0 + o1.x * b0) * li0;
            o1.y = (oacc[nb][1] * a0 + o1.y * b0) * li0;
            o2.x = (oacc[nb][2] * a1 + o2.x * b1) * li1;
            o2.y = (oacc[nb][3] * a1 + o2.y * b1) * li1;
            *(float2*)&Qs[(h * 16 + lr) * 132 + col]     = o1;
            *(float2*)&Qs[(h * 16 + lr + 8) * 132 + col] = o2;
        }
    }
    __syncthreads();
#pragma unroll
    for (int i = 0; i < 8; i++) {
        int idx = tid + i * 256;
        int hh = idx >> 9, qi = (idx >> 5) & 15, d4 = (idx & 31) * 4;
        float4 val = *(float4*)&Qs[(hh * 16 + qi) * 132 + d4];
        *(float4*)&out[((size_t)(b * NS + q0 + qi) * NHQ + hk * NG + hh) * ND + d4] = val;
    }
}

// ---------------------------------------------------------------------------
extern "C" void kernel_launch(void* const* d_in, const int* in_sizes, int n_in,
                              void* d_out, int out_size) {
    const float* q   = (const float*)d_in[0];
    const float* k   = (const float*)d_in[1];
    const float* v   = (const float*)d_in[2];
    const int*   pos = (const int*)d_in[3];
    float* out = (float*)d_out;

    dim3 gp(NS / 64, NHK, NB);
    prep_kernel<<<gp, 256>>>(k, v, pos);

    const int smem = SMEM_FLOATS * 4;
    cudaFuncSetAttribute(attn_kernel,
                         cudaFuncAttributeMaxDynamicSharedMemorySize, smem);
    dim3 ga(NS / 16, NHK, NB);
    attn_kernel<<<ga, 256, smem>>>(q, pos, out);
}

// round 8
// speedup vs baseline: 2.1334x; 1.2813x over previous
#include <cuda_runtime.h>
#include <math.h>
#include <stdint.h>

#define NB 2
#define NS 2048
#define NHQ 32
#define NHK 8
#define ND 128
#define NG 4
#define WIN 1024

// rope'd K (tf32-rounded) and tf32-rounded V, [b][hk][s][d]
__device__ float g_kr[(size_t)NB * NHK * NS * ND];
__device__ float g_vr[(size_t)NB * NHK * NS * ND];

__device__ __forceinline__ float ex2f(float x) {
    float r; asm("ex2.approx.ftz.f32 %0,%1;" : "=f"(r) : "f"(x)); return r;
}
__device__ __forceinline__ uint32_t f2tf(float x) {
    uint32_t r; asm("cvt.rna.tf32.f32 %0,%1;" : "=r"(r) : "f"(x)); return r;
}
__device__ __forceinline__ void split_tf32(float x, uint32_t& hi, uint32_t& lo) {
    uint32_t h; asm("cvt.rna.tf32.f32 %0,%1;" : "=r"(h) : "f"(x));
    float hf = __uint_as_float(h);
    uint32_t l; asm("cvt.rna.tf32.f32 %0,%1;" : "=r"(l) : "f"(x - hf));
    hi = h; lo = l;
}
__device__ __forceinline__ void mma_tf32(float* d, const uint32_t* a, const uint32_t* b) {
    asm volatile(
        "mma.sync.aligned.m16n8k8.row.col.f32.tf32.tf32.f32 "
        "{%0,%1,%2,%3},{%4,%5,%6,%7},{%8,%9},{%0,%1,%2,%3};"
        : "+f"(d[0]), "+f"(d[1]), "+f"(d[2]), "+f"(d[3])
        : "r"(a[0]), "r"(a[1]), "r"(a[2]), "r"(a[3]), "r"(b[0]), "r"(b[1]));
}
__device__ __forceinline__ uint32_t cvta(const void* p) {
    return (uint32_t)__cvta_generic_to_shared(p);
}
__device__ __forceinline__ void cpa(uint32_t d, const float* s) {
    asm volatile("cp.async.cg.shared.global [%0],[%1],16;" :: "r"(d), "l"(s));
}
#define COMMIT() asm volatile("cp.async.commit_group;")
#define WAIT1()  asm volatile("cp.async.wait_group 1;")

// smem float offsets
#define QHI_OFF 0
#define QLO_OFF 8448
#define KH_OFF  16896   /* + buf*8448 */
#define V_OFF   33792   /* + buf*8448 */
#define PS_OFF  50688
#define ML_OFF  55040
#define SMEM_FLOATS 55168

// ---------------------------------------------------------------------------
// prep: rope K -> tf32 round; V -> tf32 round; layout [b][hk][s][d]
// ---------------------------------------------------------------------------
__global__ void prep_kernel(const float* __restrict__ key,
                            const float* __restrict__ value,
                            const int* __restrict__ pos) {
    const int k0 = blockIdx.x * 64, hk = blockIdx.y, b = blockIdx.z;
    const int tid = threadIdx.x;
#pragma unroll
    for (int i = 0; i < 16; i++) {
        int idx = tid + i * 256;
        int kl = idx >> 6, dp = idx & 63;
        int token = b * NS + k0 + kl;
        float ps = (float)pos[token];
        float invf = powf(10000.0f, -((float)dp) / 64.0f);
        float sn, cs; sincosf(ps * invf, &sn, &cs);
        const float* kp = key + (size_t)token * (NHK * ND) + hk * ND;
        float x1 = kp[dp], x2 = kp[dp + 64];
        size_t ob = ((size_t)(b * NHK + hk) * NS + k0 + kl) * ND;
        g_kr[ob + dp]      = __uint_as_float(f2tf(x1 * cs - x2 * sn));
        g_kr[ob + dp + 64] = __uint_as_float(f2tf(x2 * cs + x1 * sn));
    }
#pragma unroll
    for (int i = 0; i < 8; i++) {
        int idx = tid + i * 256;
        int kl = idx >> 5, c4 = (idx & 31) * 4;
        int token = b * NS + k0 + kl;
        float4 v4 = *(const float4*)(value + (size_t)token * (NHK * ND) + hk * ND + c4);
        float4 o;
        o.x = __uint_as_float(f2tf(v4.x));
        o.y = __uint_as_float(f2tf(v4.y));
        o.z = __uint_as_float(f2tf(v4.z));
        o.w = __uint_as_float(f2tf(v4.w));
        *(float4*)(g_vr + ((size_t)(b * NHK + hk) * NS + k0 + kl) * ND + c4) = o;
    }
}

// ---------------------------------------------------------------------------
// attention: block = (16 queries, hk, b); 8 warps = 4 heads x 2 key-halves
// ---------------------------------------------------------------------------
__global__ void __launch_bounds__(256, 1)
attn_kernel(const float* __restrict__ query, const int* __restrict__ pos,
            float* __restrict__ out) {
    extern __shared__ float smf[];
    float*    Qs = smf + QHI_OFF;               // fp32 O-merge reuse in epilogue
    uint32_t* QH = (uint32_t*)(smf + QHI_OFF);  // 64 x 132 tf32 bits
    uint32_t* QL = (uint32_t*)(smf + QLO_OFF);
    float*    Ps = smf + PS_OFF;                // 64 x 68 (sincos / P)
    float*    ML = smf + ML_OFF;

    const int qt = blockIdx.x, hk = blockIdx.y, b = blockIdx.z;
    const int q0 = qt * 16, tid = threadIdx.x;
    const int w = tid >> 5, lane = tid & 31;
    const int h = w & 3, kh = w >> 2;
    const int lr = lane >> 2, lc = lane & 3;
    const float CF = 1.4426950408889634f * 0.08838834764831845f;

    // sincos table
#pragma unroll
    for (int i = 0; i < 4; i++) {
        int idx = tid + i * 256;
        int qi = idx >> 6, dp = idx & 63;
        float ps = (float)pos[b * NS + q0 + qi];
        float invf = powf(10000.0f, -((float)dp) / 64.0f);
        float sn, cs; sincosf(ps * invf, &sn, &cs);
        Ps[idx] = cs; Ps[1024 + idx] = sn;
    }
    __syncthreads();
    // rope + scale + split Q
#pragma unroll
    for (int i = 0; i < 16; i++) {
        int idx = tid + i * 256;
        int row = idx >> 6, dp = idx & 63;
        int qi = row & 15, hh = row >> 4;
        const float* qp = query + ((size_t)(b * NS + q0 + qi) * NHQ + (hk * NG + hh)) * ND;
        float x1 = qp[dp], x2 = qp[dp + 64];
        float cs = Ps[qi * 64 + dp], sn = Ps[1024 + qi * 64 + dp];
        float o1 = (x1 * cs - x2 * sn) * CF;
        float o2 = (x2 * cs + x1 * sn) * CF;
        uint32_t hi, lo;
        split_tf32(o1, hi, lo);
        QH[row * 132 + dp] = hi; QL[row * 132 + dp] = lo;
        split_tf32(o2, hi, lo);
        QH[row * 132 + dp + 64] = hi; QL[row * 132 + dp + 64] = lo;
    }
    __syncthreads();

    int jmin = q0 - (WIN - 1); if (jmin < 0) jmin = 0; jmin &= ~63;
    const int nt = (q0 + 15 - jmin) / 64 + 1;

    const float* kb = g_kr + (size_t)(b * NHK + hk) * NS * ND;
    const float* vb = g_vr + (size_t)(b * NHK + hk) * NS * ND;
    const int cr = tid >> 5, cc4 = (tid & 31) * 4;

    // prologue: tile 0 (KH + V, one group)
#pragma unroll
    for (int i = 0; i < 8; i++) {
        cpa(cvta(smf + KH_OFF + (cr + i * 8) * 132 + cc4), kb + (size_t)(jmin + cr + i * 8) * ND + cc4);
        cpa(cvta(smf + V_OFF  + (cr + i * 8) * 132 + cc4), vb + (size_t)(jmin + cr + i * 8) * ND + cc4);
    }
    COMMIT();

    float oacc[16][4];
#pragma unroll
    for (int nb = 0; nb < 16; nb++)
#pragma unroll
        for (int e = 0; e < 4; e++) oacc[nb][e] = 0.0f;
    float mcur0 = -1e30f, mcur1 = -1e30f, lcur0 = 0.0f, lcur1 = 0.0f;

    for (int t = 0; t < nt; t++) {
        const int k0 = jmin + t * 64, buf = t & 1;

        // prefetch tile t+1 into the other buffer (safe: its readers synced last iter)
        if (t + 1 < nt) {
            const float* ks = kb + (size_t)(k0 + 64) * ND;
            const float* vs = vb + (size_t)(k0 + 64) * ND;
            uint32_t kd = cvta(smf + KH_OFF + (1 - buf) * 8448);
            uint32_t vd = cvta(smf + V_OFF  + (1 - buf) * 8448);
#pragma unroll
            for (int i = 0; i < 8; i++) {
                cpa(kd + ((cr + i * 8) * 132 + cc4) * 4, ks + (size_t)(cr + i * 8) * ND + cc4);
                cpa(vd + ((cr + i * 8) * 132 + cc4) * 4, vs + (size_t)(cr + i * 8) * ND + cc4);
            }
        }
        COMMIT();          // (possibly empty) group for t+1
        WAIT1();           // tile t's group done
        __syncthreads();   // visible to all warps

        const uint32_t* KH = (const uint32_t*)(smf + KH_OFF + buf * 8448);
        const uint32_t* Vu = (const uint32_t*)(smf + V_OFF  + buf * 8448);

        // ---- QK^T, 2-term tf32 (exact Q x rounded K) ----
        float sacc[4][4];
#pragma unroll
        for (int nb = 0; nb < 4; nb++)
#pragma unroll
            for (int e = 0; e < 4; e++) sacc[nb][e] = 0.0f;

#pragma unroll
        for (int c = 0; c < 16; c++) {
            uint32_t ah[4], al[4];
            ah[0] = QH[(h * 16 + lr) * 132 + c * 8 + lc];
            ah[1] = QH[(h * 16 + lr + 8) * 132 + c * 8 + lc];
            ah[2] = QH[(h * 16 + lr) * 132 + c * 8 + lc + 4];
            ah[3] = QH[(h * 16 + lr + 8) * 132 + c * 8 + lc + 4];
            al[0] = QL[(h * 16 + lr) * 132 + c * 8 + lc];
            al[1] = QL[(h * 16 + lr + 8) * 132 + c * 8 + lc];
            al[2] = QL[(h * 16 + lr) * 132 + c * 8 + lc + 4];
            al[3] = QL[(h * 16 + lr + 8) * 132 + c * 8 + lc + 4];
#pragma unroll
            for (int nb = 0; nb < 4; nb++) {
                int krow = kh * 32 + nb * 8 + lr;
                uint32_t bh[2];
                bh[0] = KH[krow * 132 + c * 8 + lc];
                bh[1] = KH[krow * 132 + c * 8 + lc + 4];
                mma_tf32(sacc[nb], ah, bh);
                mma_tf32(sacc[nb], al, bh);
            }
        }

        // ---- mask ----
        const int i0 = q0 + lr, i1 = i0 + 8;
        if (!((k0 + 63 <= q0) && (q0 + 15 - k0 < WIN))) {
#pragma unroll
            for (int nb = 0; nb < 4; nb++) {
                int j0 = k0 + kh * 32 + nb * 8 + 2 * lc;
                if (j0 > i0     || i0 - j0 >= WIN)     sacc[nb][0] = -1e38f;
                if (j0 + 1 > i0 || i0 - j0 - 1 >= WIN) sacc[nb][1] = -1e38f;
                if (j0 > i1     || i1 - j0 >= WIN)     sacc[nb][2] = -1e38f;
                if (j0 + 1 > i1 || i1 - j0 - 1 >= WIN) sacc[nb][3] = -1e38f;
            }
        }

        // ---- online softmax (per warp) ----
        float r0 = -1e38f, r1 = -1e38f;
#pragma unroll
        for (int nb = 0; nb < 4; nb++) {
            r0 = fmaxf(r0, fmaxf(sacc[nb][0], sacc[nb][1]));
            r1 = fmaxf(r1, fmaxf(sacc[nb][2], sacc[nb][3]));
        }
        r0 = fmaxf(r0, __shfl_xor_sync(0xffffffffu, r0, 1));
        r0 = fmaxf(r0, __shfl_xor_sync(0xffffffffu, r0, 2));
        r1 = fmaxf(r1, __shfl_xor_sync(0xffffffffu, r1, 1));
        r1 = fmaxf(r1, __shfl_xor_sync(0xffffffffu, r1, 2));
        float mn0 = fmaxf(mcur0, r0), mn1 = fmaxf(mcur1, r1);
        float f0 = ex2f(mcur0 - mn0), f1 = ex2f(mcur1 - mn1);
        mcur0 = mn0; mcur1 = mn1;
        lcur0 *= f0; lcur1 *= f1;
        float s0 = 0.0f, s1 = 0.0f;
#pragma unroll
        for (int nb = 0; nb < 4; nb++) {
            float p00 = ex2f(sacc[nb][0] - mn0), p01 = ex2f(sacc[nb][1] - mn0);
            float p10 = ex2f(sacc[nb][2] - mn1), p11 = ex2f(sacc[nb][3] - mn1);
            s0 += p00 + p01; s1 += p10 + p11;
            int col = kh * 32 + nb * 8 + 2 * lc;
            *(float2*)&Ps[(h * 16 + lr) * 68 + col]     = make_float2(p00, p01);
            *(float2*)&Ps[(h * 16 + lr + 8) * 68 + col] = make_float2(p10, p11);
        }
        lcur0 += s0; lcur1 += s1;
#pragma unroll
        for (int nb = 0; nb < 16; nb++) {
            oacc[nb][0] *= f0; oacc[nb][1] *= f0;
            oacc[nb][2] *= f1; oacc[nb][3] *= f1;
        }
        __syncwarp();

        // ---- P @ V ----
#pragma unroll
        for (int kc = 0; kc < 4; kc++) {
            uint32_t ap[4];
            ap[0] = f2tf(Ps[(h * 16 + lr) * 68 + kh * 32 + kc * 8 + lc]);
            ap[1] = f2tf(Ps[(h * 16 + lr + 8) * 68 + kh * 32 + kc * 8 + lc]);
            ap[2] = f2tf(Ps[(h * 16 + lr) * 68 + kh * 32 + kc * 8 + lc + 4]);
            ap[3] = f2tf(Ps[(h * 16 + lr + 8) * 68 + kh * 32 + kc * 8 + lc + 4]);
#pragma unroll
            for (int nb = 0; nb < 16; nb++) {
                uint32_t bv[2];
                bv[0] = Vu[(kh * 32 + kc * 8 + lc) * 132 + nb * 8 + lr];
                bv[1] = Vu[(kh * 32 + kc * 8 + lc + 4) * 132 + nb * 8 + lr];
                mma_tf32(oacc[nb], ap, bv);
            }
        }
        __syncthreads();   // tile t fully consumed; next iter may overwrite
    }

    // ---- epilogue ----
    lcur0 += __shfl_xor_sync(0xffffffffu, lcur0, 1);
    lcur0 += __shfl_xor_sync(0xffffffffu, lcur0, 2);
    lcur1 += __shfl_xor_sync(0xffffffffu, lcur1, 1);
    lcur1 += __shfl_xor_sync(0xffffffffu, lcur1, 2);

    if (kh == 1) {
        if (lc == 0) {
            ML[h * 16 + lr] = mcur0;      ML[h * 16 + lr + 8] = mcur1;
            ML[64 + h * 16 + lr] = lcur0; ML[64 + h * 16 + lr + 8] = lcur1;
        }
#pragma unroll
        for (int nb = 0; nb < 16; nb++) {
            int col = nb * 8 + 2 * lc;
            *(float2*)&Qs[(h * 16 + lr) * 132 + col]     = make_float2(oacc[nb][0], oacc[nb][1]);
            *(float2*)&Qs[(h * 16 + lr + 8) * 132 + col] = make_float2(oacc[nb][2], oacc[nb][3]);
        }
    }
    __syncthreads();
    if (kh == 0) {
        float m1a = ML[h * 16 + lr],      m1b = ML[h * 16 + lr + 8];
        float l1a = ML[64 + h * 16 + lr], l1b = ML[64 + h * 16 + lr + 8];
        float mfa = fmaxf(mcur0, m1a), mfb = fmaxf(mcur1, m1b);
        float a0 = ex2f(mcur0 - mfa), b0 = ex2f(m1a - mfa);
        float a1 = ex2f(mcur1 - mfb), b1 = ex2f(m1b - mfb);
        float li0 = 1.0f / (lcur0 * a0 + l1a * b0);
        float li1 = 1.0f / (lcur1 * a1 + l1b * b1);
#pragma unroll
        for (int nb = 0; nb < 16; nb++) {
            int col = nb * 8 + 2 * lc;
            float2 o1 = *(float2*)&Qs[(h * 16 + lr) * 132 + col];
            float2 o2 = *(float2*)&Qs[(h * 16 + lr + 8) * 132 + col];
            o1.x = (oacc[nb][0] * a0 + o1.x * b0) * li0;
            o1.y = (oacc[nb][1] * a0 + o1.y * b0) * li0;
            o2.x = (oacc[nb][2] * a1 + o2.x * b1) * li1;
            o2.y = (oacc[nb][3] * a1 + o2.y * b1) * li1;
            *(float2*)&Qs[(h * 16 + lr) * 132 + col]     = o1;
            *(float2*)&Qs[(h * 16 + lr + 8) * 132 + col] = o2;
        }
    }
    __syncthreads();
#pragma unroll
    for (int i = 0; i < 8; i++) {
        int idx = tid + i * 256;
        int hh = idx >> 9, qi = (idx >> 5) & 15, d4 = (idx & 31) * 4;
        float4 val = *(float4*)&Qs[(hh * 16 + qi) * 132 + d4];
        *(float4*)&out[((size_t)(b * NS + q0 + qi) * NHQ + hk * NG + hh) * ND + d4] = val;
    }
}

// ---------------------------------------------------------------------------
extern "C" void kernel_launch(void* const* d_in, const int* in_sizes, int n_in,
                              void* d_out, int out_size) {
    const float* q   = (const float*)d_in[0];
    const float* k   = (const float*)d_in[1];
    const float* v   = (const float*)d_in[2];
    const int*   pos = (const int*)d_in[3];
    float* out = (float*)d_out;

    dim3 gp(NS / 64, NHK, NB);
    prep_kernel<<<gp, 256>>>(k, v, pos);

    const int smem = SMEM_FLOATS * 4;
    cudaFuncSetAttribute(attn_kernel,
                         cudaFuncAttributeMaxDynamicSharedMemorySize, smem);
    dim3 ga(NS / 16, NHK, NB);
    attn_kernel<<<ga, 256, smem>>>(q, pos, out);
}

// round 9
// speedup vs baseline: 2.6002x; 1.2188x over previous
#include <cuda_runtime.h>
#include <math.h>
#include <stdint.h>

#define NB 2
#define NS 2048
#define NHQ 32
#define NHK 8
#define ND 128
#define NG 4
#define WIN 1024

// rope'd K (tf32-rounded) and tf32-rounded V, [b][hk][s][d]
__device__ float g_kr[(size_t)NB * NHK * NS * ND];
__device__ float g_vr[(size_t)NB * NHK * NS * ND];

__device__ __forceinline__ float ex2f(float x) {
    float r; asm("ex2.approx.ftz.f32 %0,%1;" : "=f"(r) : "f"(x)); return r;
}
__device__ __forceinline__ uint32_t f2tf(float x) {
    uint32_t r; asm("cvt.rna.tf32.f32 %0,%1;" : "=r"(r) : "f"(x)); return r;
}
__device__ __forceinline__ void mma_tf32(float* d, const uint32_t* a, const uint32_t* b) {
    asm volatile(
        "mma.sync.aligned.m16n8k8.row.col.f32.tf32.tf32.f32 "
        "{%0,%1,%2,%3},{%4,%5,%6,%7},{%8,%9},{%0,%1,%2,%3};"
        : "+f"(d[0]), "+f"(d[1]), "+f"(d[2]), "+f"(d[3])
        : "r"(a[0]), "r"(a[1]), "r"(a[2]), "r"(a[3]), "r"(b[0]), "r"(b[1]));
}
__device__ __forceinline__ uint32_t cvta(const void* p) {
    return (uint32_t)__cvta_generic_to_shared(p);
}
__device__ __forceinline__ void cpa(uint32_t d, const float* s) {
    asm volatile("cp.async.cg.shared.global [%0],[%1],16;" :: "r"(d), "l"(s));
}
#define COMMIT() asm volatile("cp.async.commit_group;")
#define WAIT1()  asm volatile("cp.async.wait_group 1;")

// smem float offsets
#define QS_OFF 0                     /* 64x132: Q tf32 staging, later O merge */
#define KH_OFF 8448                  /* + buf*8448 */
#define V_OFF  25344                 /* + buf*8448 */
#define PS_OFF 42240                 /* 64x68: sincos / P */
#define ML_OFF 46592
#define SMEM_FLOATS 46720

// ---------------------------------------------------------------------------
__global__ void prep_kernel(const float* __restrict__ key,
                            const float* __restrict__ value,
                            const int* __restrict__ pos) {
    const int k0 = blockIdx.x * 64, hk = blockIdx.y, b = blockIdx.z;
    const int tid = threadIdx.x;
#pragma unroll
    for (int i = 0; i < 16; i++) {
        int idx = tid + i * 256;
        int kl = idx >> 6, dp = idx & 63;
        int token = b * NS + k0 + kl;
        float ps = (float)pos[token];
        float invf = powf(10000.0f, -((float)dp) / 64.0f);
        float sn, cs; sincosf(ps * invf, &sn, &cs);
        const float* kp = key + (size_t)token * (NHK * ND) + hk * ND;
        float x1 = kp[dp], x2 = kp[dp + 64];
        size_t ob = ((size_t)(b * NHK + hk) * NS + k0 + kl) * ND;
        g_kr[ob + dp]      = __uint_as_float(f2tf(x1 * cs - x2 * sn));
        g_kr[ob + dp + 64] = __uint_as_float(f2tf(x2 * cs + x1 * sn));
    }
#pragma unroll
    for (int i = 0; i < 8; i++) {
        int idx = tid + i * 256;
        int kl = idx >> 5, c4 = (idx & 31) * 4;
        int token = b * NS + k0 + kl;
        float4 v4 = *(const float4*)(value + (size_t)token * (NHK * ND) + hk * ND + c4);
        float4 o;
        o.x = __uint_as_float(f2tf(v4.x));
        o.y = __uint_as_float(f2tf(v4.y));
        o.z = __uint_as_float(f2tf(v4.z));
        o.w = __uint_as_float(f2tf(v4.w));
        *(float4*)(g_vr + ((size_t)(b * NHK + hk) * NS + k0 + kl) * ND + c4) = o;
    }
}

// ---------------------------------------------------------------------------
// attention: block = (16 queries, hk, b); 8 warps = 4 heads x 2 key-halves
// Q fragments live in registers (single tf32); K,V stream via cp.async.
// ---------------------------------------------------------------------------
__global__ void __launch_bounds__(256, 1)
attn_kernel(const float* __restrict__ query, const int* __restrict__ pos,
            float* __restrict__ out) {
    extern __shared__ float smf[];
    float*    Qs = smf + QS_OFF;
    uint32_t* QH = (uint32_t*)(smf + QS_OFF);
    float*    Ps = smf + PS_OFF;
    float*    ML = smf + ML_OFF;

    const int qt = blockIdx.x, hk = blockIdx.y, b = blockIdx.z;
    const int q0 = qt * 16, tid = threadIdx.x;
    const int w = tid >> 5, lane = tid & 31;
    const int h = w & 3, kh = w >> 2;
    const int lr = lane >> 2, lc = lane & 3;
    const float CF = 1.4426950408889634f * 0.08838834764831845f;

    int jmin = q0 - (WIN - 1); if (jmin < 0) jmin = 0; jmin &= ~63;
    const int nt = (q0 + 15 - jmin) / 64 + 1;
    const float* kb = g_kr + (size_t)(b * NHK + hk) * NS * ND;
    const float* vb = g_vr + (size_t)(b * NHK + hk) * NS * ND;
    const int cr = tid >> 5, cc4 = (tid & 31) * 4;

    // tile 0 copies first (overlap DRAM with rope math)
#pragma unroll
    for (int i = 0; i < 8; i++) {
        cpa(cvta(smf + KH_OFF + (cr + i * 8) * 132 + cc4), kb + (size_t)(jmin + cr + i * 8) * ND + cc4);
        cpa(cvta(smf + V_OFF  + (cr + i * 8) * 132 + cc4), vb + (size_t)(jmin + cr + i * 8) * ND + cc4);
    }
    COMMIT();

    // sincos table
#pragma unroll
    for (int i = 0; i < 4; i++) {
        int idx = tid + i * 256;
        int qi = idx >> 6, dp = idx & 63;
        float ps = (float)pos[b * NS + q0 + qi];
        float invf = powf(10000.0f, -((float)dp) / 64.0f);
        float sn, cs; sincosf(ps * invf, &sn, &cs);
        Ps[idx] = cs; Ps[1024 + idx] = sn;
    }
    __syncthreads();
    // rope + scale + round Q -> QH (single tf32)
#pragma unroll
    for (int i = 0; i < 16; i++) {
        int idx = tid + i * 256;
        int row = idx >> 6, dp = idx & 63;
        int qi = row & 15, hh = row >> 4;
        const float* qp = query + ((size_t)(b * NS + q0 + qi) * NHQ + (hk * NG + hh)) * ND;
        float x1 = qp[dp], x2 = qp[dp + 64];
        float cs = Ps[qi * 64 + dp], sn = Ps[1024 + qi * 64 + dp];
        QH[row * 132 + dp]      = f2tf((x1 * cs - x2 * sn) * CF);
        QH[row * 132 + dp + 64] = f2tf((x2 * cs + x1 * sn) * CF);
    }
    __syncthreads();

    // hoist Q fragments to registers (read QH once)
    uint32_t qf[64];
#pragma unroll
    for (int c = 0; c < 16; c++) {
        qf[c * 4 + 0] = QH[(h * 16 + lr) * 132 + c * 8 + lc];
        qf[c * 4 + 1] = QH[(h * 16 + lr + 8) * 132 + c * 8 + lc];
        qf[c * 4 + 2] = QH[(h * 16 + lr) * 132 + c * 8 + lc + 4];
        qf[c * 4 + 3] = QH[(h * 16 + lr + 8) * 132 + c * 8 + lc + 4];
    }

    float oacc[16][4];
#pragma unroll
    for (int nb = 0; nb < 16; nb++)
#pragma unroll
        for (int e = 0; e < 4; e++) oacc[nb][e] = 0.0f;
    float mcur0 = -1e30f, mcur1 = -1e30f, lcur0 = 0.0f, lcur1 = 0.0f;

    for (int t = 0; t < nt; t++) {
        const int k0 = jmin + t * 64, buf = t & 1;

        if (t + 1 < nt) {
            const float* ks = kb + (size_t)(k0 + 64) * ND;
            const float* vs = vb + (size_t)(k0 + 64) * ND;
            uint32_t kd = cvta(smf + KH_OFF + (1 - buf) * 8448);
            uint32_t vd = cvta(smf + V_OFF  + (1 - buf) * 8448);
#pragma unroll
            for (int i = 0; i < 8; i++) {
                cpa(kd + ((cr + i * 8) * 132 + cc4) * 4, ks + (size_t)(cr + i * 8) * ND + cc4);
                cpa(vd + ((cr + i * 8) * 132 + cc4) * 4, vs + (size_t)(cr + i * 8) * ND + cc4);
            }
        }
        COMMIT();
        WAIT1();
        __syncthreads();

        const uint32_t* KH = (const uint32_t*)(smf + KH_OFF + buf * 8448);
        const uint32_t* Vu = (const uint32_t*)(smf + V_OFF  + buf * 8448);

        // ---- QK^T, single tf32 (Q regs x K smem) ----
        float sacc[4][4];
#pragma unroll
        for (int nb = 0; nb < 4; nb++)
#pragma unroll
            for (int e = 0; e < 4; e++) sacc[nb][e] = 0.0f;

#pragma unroll
        for (int c = 0; c < 16; c++) {
#pragma unroll
            for (int nb = 0; nb < 4; nb++) {
                int krow = kh * 32 + nb * 8 + lr;
                uint32_t bh[2];
                bh[0] = KH[krow * 132 + c * 8 + lc];
                bh[1] = KH[krow * 132 + c * 8 + lc + 4];
                mma_tf32(sacc[nb], qf + c * 4, bh);
            }
        }

        // ---- mask ----
        const int i0 = q0 + lr, i1 = i0 + 8;
        if (!((k0 + 63 <= q0) && (q0 + 15 - k0 < WIN))) {
#pragma unroll
            for (int nb = 0; nb < 4; nb++) {
                int j0 = k0 + kh * 32 + nb * 8 + 2 * lc;
                if (j0 > i0     || i0 - j0 >= WIN)     sacc[nb][0] = -1e38f;
                if (j0 + 1 > i0 || i0 - j0 - 1 >= WIN) sacc[nb][1] = -1e38f;
                if (j0 > i1     || i1 - j0 >= WIN)     sacc[nb][2] = -1e38f;
                if (j0 + 1 > i1 || i1 - j0 - 1 >= WIN) sacc[nb][3] = -1e38f;
            }
        }

        // ---- online softmax (per warp) ----
        float r0 = -1e38f, r1 = -1e38f;
#pragma unroll
        for (int nb = 0; nb < 4; nb++) {
            r0 = fmaxf(r0, fmaxf(sacc[nb][0], sacc[nb][1]));
            r1 = fmaxf(r1, fmaxf(sacc[nb][2], sacc[nb][3]));
        }
        r0 = fmaxf(r0, __shfl_xor_sync(0xffffffffu, r0, 1));
        r0 = fmaxf(r0, __shfl_xor_sync(0xffffffffu, r0, 2));
        r1 = fmaxf(r1, __shfl_xor_sync(0xffffffffu, r1, 1));
        r1 = fmaxf(r1, __shfl_xor_sync(0xffffffffu, r1, 2));
        float mn0 = fmaxf(mcur0, r0), mn1 = fmaxf(mcur1, r1);
        float f0 = ex2f(mcur0 - mn0), f1 = ex2f(mcur1 - mn1);
        mcur0 = mn0; mcur1 = mn1;
        lcur0 *= f0; lcur1 *= f1;
        float s0 = 0.0f, s1 = 0.0f;
#pragma unroll
        for (int nb = 0; nb < 4; nb++) {
            float p00 = ex2f(sacc[nb][0] - mn0), p01 = ex2f(sacc[nb][1] - mn0);
            float p10 = ex2f(sacc[nb][2] - mn1), p11 = ex2f(sacc[nb][3] - mn1);
            s0 += p00 + p01; s1 += p10 + p11;
            int col = kh * 32 + nb * 8 + 2 * lc;
            *(float2*)&Ps[(h * 16 + lr) * 68 + col]     = make_float2(p00, p01);
            *(float2*)&Ps[(h * 16 + lr + 8) * 68 + col] = make_float2(p10, p11);
        }
        lcur0 += s0; lcur1 += s1;
#pragma unroll
        for (int nb = 0; nb < 16; nb++) {
            oacc[nb][0] *= f0; oacc[nb][1] *= f0;
            oacc[nb][2] *= f1; oacc[nb][3] *= f1;
        }
        __syncwarp();

        // ---- P @ V ----
#pragma unroll
        for (int kc = 0; kc < 4; kc++) {
            uint32_t ap[4];
            ap[0] = f2tf(Ps[(h * 16 + lr) * 68 + kh * 32 + kc * 8 + lc]);
            ap[1] = f2tf(Ps[(h * 16 + lr + 8) * 68 + kh * 32 + kc * 8 + lc]);
            ap[2] = f2tf(Ps[(h * 16 + lr) * 68 + kh * 32 + kc * 8 + lc + 4]);
            ap[3] = f2tf(Ps[(h * 16 + lr + 8) * 68 + kh * 32 + kc * 8 + lc + 4]);
#pragma unroll
            for (int nb = 0; nb < 16; nb++) {
                uint32_t bv[2];
                bv[0] = Vu[(kh * 32 + kc * 8 + lc) * 132 + nb * 8 + lr];
                bv[1] = Vu[(kh * 32 + kc * 8 + lc + 4) * 132 + nb * 8 + lr];
                mma_tf32(oacc[nb], ap, bv);
            }
        }
        __syncthreads();
    }

    // ---- epilogue ----
    lcur0 += __shfl_xor_sync(0xffffffffu, lcur0, 1);
    lcur0 += __shfl_xor_sync(0xffffffffu, lcur0, 2);
    lcur1 += __shfl_xor_sync(0xffffffffu, lcur1, 1);
    lcur1 += __shfl_xor_sync(0xffffffffu, lcur1, 2);

    if (kh == 1) {
        if (lc == 0) {
            ML[h * 16 + lr] = mcur0;      ML[h * 16 + lr + 8] = mcur1;
            ML[64 + h * 16 + lr] = lcur0; ML[64 + h * 16 + lr + 8] = lcur1;
        }
#pragma unroll
        for (int nb = 0; nb < 16; nb++) {
            int col = nb * 8 + 2 * lc;
            *(float2*)&Qs[(h * 16 + lr) * 132 + col]     = make_float2(oacc[nb][0], oacc[nb][1]);
            *(float2*)&Qs[(h * 16 + lr + 8) * 132 + col] = make_float2(oacc[nb][2], oacc[nb][3]);
        }
    }
    __syncthreads();
    if (kh == 0) {
        float m1a = ML[h * 16 + lr],      m1b = ML[h * 16 + lr + 8];
        float l1a = ML[64 + h * 16 + lr], l1b = ML[64 + h * 16 + lr + 8];
        float mfa = fmaxf(mcur0, m1a), mfb = fmaxf(mcur1, m1b);
        float a0 = ex2f(mcur0 - mfa), b0 = ex2f(m1a - mfa);
        float a1 = ex2f(mcur1 - mfb), b1 = ex2f(m1b - mfb);
        float li0 = 1.0f / (lcur0 * a0 + l1a * b0);
        float li1 = 1.0f / (lcur1 * a1 + l1b * b1);
#pragma unroll
        for (int nb = 0; nb < 16; nb++) {
            int col = nb * 8 + 2 * lc;
            float2 o1 = *(float2*)&Qs[(h * 16 + lr) * 132 + col];
            float2 o2 = *(float2*)&Qs[(h * 16 + lr + 8) * 132 + col];
            o1.x = (oacc[nb][0] * a0 + o1.x * b0) * li0;
            o1.y = (oacc[nb][1] * a0 + o1.y * b0) * li0;
            o2.x = (oacc[nb][2] * a1 + o2.x * b1) * li1;
            o2.y = (oacc[nb][3] * a1 + o2.y * b1) * li1;
            *(float2*)&Qs[(h * 16 + lr) * 132 + col]     = o1;
            *(float2*)&Qs[(h * 16 + lr + 8) * 132 + col] = o2;
        }
    }
    __syncthreads();
#pragma unroll
    for (int i = 0; i < 8; i++) {
        int idx = tid + i * 256;
        int hh = idx >> 9, qi = (idx >> 5) & 15, d4 = (idx & 31) * 4;
        float4 val = *(float4*)&Qs[(hh * 16 + qi) * 132 + d4];
        *(float4*)&out[((size_t)(b * NS + q0 + qi) * NHQ + hk * NG + hh) * ND + d4] = val;
    }
}

// ---------------------------------------------------------------------------
extern "C" void kernel_launch(void* const* d_in, const int* in_sizes, int n_in,
                              void* d_out, int out_size) {
    const float* q   = (const float*)d_in[0];
    const float* k   = (const float*)d_in[1];
    const float* v   = (const float*)d_in[2];
    const int*   pos = (const int*)d_in[3];
    float* out = (float*)d_out;

    dim3 gp(NS / 64, NHK, NB);
    prep_kernel<<<gp, 256>>>(k, v, pos);

    const int smem = SMEM_FLOATS * 4;
    cudaFuncSetAttribute(attn_kernel,
                         cudaFuncAttributeMaxDynamicSharedMemorySize, smem);
    dim3 ga(NS / 16, NHK, NB);
    attn_kernel<<<ga, 256, smem>>>(q, pos, out);
}